// round 5
// baseline (speedup 1.0000x reference)
#include <cuda_runtime.h>
#include <cuda_bf16.h>

#define NN     50000
#define SS     2048
#define KK     64
#define HH     128
#define EE     524288
#define LL     5
#define MROWS  (SS*KK)      // 131072

// ---------------- scratch (device globals; no allocations) ----------------
__device__ unsigned g_Mbp[HH*HH];          // folded init weight, (bh|bl<<16), [n][k]
__device__ unsigned g_w1bp[LL*HH*HH];
__device__ unsigned g_w2bp[LL*HH*HH];
__device__ unsigned g_mp2bp[LL*2*HH*HH];   // [l][half][n][k_local]
__device__ float    g_vlogp[HH];
__device__ float    g_bias0[HH];
__device__ float    g_root[2*HH];
__device__ unsigned g_xp[NN*HH];           // packed x
__device__ unsigned g_zp[MROWS*HH];        // packed agg output
__device__ unsigned g_tp[MROWS*HH];        // packed t
__device__ float    g_z2[MROWS*HH];        // fp32 z2 (for scatter)
__device__ unsigned g_z2p[MROWS*HH];       // packed z2 (for mp2)
__device__ float    g_u[MROWS*HH];
__device__ float    g_xagg[NN*HH];
__device__ unsigned g_xaggp[NN*HH];        // packed xagg*inv
__device__ float    g_inv[NN];
__device__ int      g_cnt[NN];
__device__ float    g_stats[2*HH];

// ---------------- helpers ----------------
__device__ __forceinline__ unsigned pack_a(float v) {
    __nv_bfloat16 hi = __float2bfloat16_rn(v);
    __nv_bfloat16 lo = __float2bfloat16_rn(v - __bfloat162float(hi));
    return (unsigned)__bfloat16_as_ushort(hi)
         | ((unsigned)__bfloat16_as_ushort(lo) << 16);
}
__device__ __forceinline__ unsigned smem_u32(const void* p) {
    unsigned a;
    asm("{ .reg .u64 t; cvta.to.shared.u64 t, %1; cvt.u32.u64 %0, t; }" : "=r"(a) : "l"(p));
    return a;
}

#define CP16(dst, src) \
    asm volatile("cp.async.cg.shared.global [%0], [%1], 16;" :: "r"(dst), "l"(src) : "memory")
#define CPCOMMIT() asm volatile("cp.async.commit_group;" ::: "memory")
#define CPWAIT(n)  asm volatile("cp.async.wait_group %0;" :: "n"(n) : "memory")

#define LDSM4(R0,R1,R2,R3,ADDR) \
    asm volatile("ldmatrix.sync.aligned.m8n8.x4.shared.b16 {%0,%1,%2,%3}, [%4];" \
        : "=r"(R0),"=r"(R1),"=r"(R2),"=r"(R3) : "r"(ADDR))

#define MMA_BF16(C, A0,A1,A2,A3, B0,B1) \
    asm volatile("mma.sync.aligned.m16n8k16.row.col.f32.bf16.bf16.f32 " \
        "{%0,%1,%2,%3},{%4,%5,%6,%7},{%8,%9},{%0,%1,%2,%3};" \
        : "+f"(C[0]),"+f"(C[1]),"+f"(C[2]),"+f"(C[3]) \
        : "r"(A0),"r"(A1),"r"(A2),"r"(A3),"r"(B0),"r"(B1))

// smem geometry: B rows 528B (128 u32 + 16B pad), A rows 144B (32 u32 + 16B pad)
#define BROWB  528
#define AROWB  144
#define BHALF  (128*BROWB)      // 67584
#define ABUF   (128*AROWB)      // 18432

// ---------------- weight folding / packing ----------------
__global__ void pack_x_kernel(const float* __restrict__ x) {
    int idx = blockIdx.x*256 + threadIdx.x;   // covers NN*HH exactly
    g_xp[idx] = pack_a(x[idx]);
}

__global__ void fold_M_kernel(const float* __restrict__ npw, const float* __restrict__ ipw) {
    int k = blockIdx.x;       // input channel
    int n = threadIdx.x;      // output channel
    float s = 0.f;
    for (int c = 0; c < HH; c++) s += npw[k*HH + c] * ipw[c*HH + n];
    g_Mbp[n*HH + k] = pack_a(s);
}

__global__ void fold_vec_kernel(const float* __restrict__ lpw, const float* __restrict__ npb,
                                const float* __restrict__ lpb, const float* __restrict__ remb,
                                const float* __restrict__ ipw, const float* __restrict__ ipb) {
    int j = threadIdx.x;
    float v = 0.f, b = ipb[j], r0 = 0.f, r1 = 0.f;
    for (int k = 0; k < HH; k++) {
        float wa = ipw[k*HH + j];
        float wb = ipw[(HH + k)*HH + j];
        float wc = ipw[(2*HH + k)*HH + j];
        v  += lpw[k] * wb;
        b  += npb[k] * wa + lpb[k] * wb;
        r0 += remb[k] * wc;
        r1 += remb[HH + k] * wc;
    }
    g_vlogp[j] = v;
    g_bias0[j] = b;
    g_root[j] = r0;
    g_root[HH + j] = r1;
}

// W [L][128 k][128 n] -> blob [L][n][k] packed
__global__ void pack_w128(const float* __restrict__ W, unsigned* __restrict__ out) {
    int l = blockIdx.y;
    int idx = blockIdx.x*256 + threadIdx.x;    // 0..16383
    int k = idx >> 7, n = idx & 127;
    out[(size_t)l*16384 + n*128 + k] = pack_a(W[(size_t)l*16384 + idx]);
}
// W [L][256 k][128 n] -> blob [L][half][n][k_local]
__global__ void pack_w256(const float* __restrict__ W, unsigned* __restrict__ out) {
    int l = blockIdx.y;
    int idx = blockIdx.x*256 + threadIdx.x;    // 0..32767
    int kg = idx >> 7, n = idx & 127;
    int h = kg >> 7, kl = kg & 127;
    out[(size_t)l*32768 + h*16384 + n*128 + kl] = pack_a(W[(size_t)l*32768 + idx]);
}

// ---------------- counts for scatter-mean ----------------
__global__ void zero_cnt_kernel() {
    int i = blockIdx.x*blockDim.x + threadIdx.x;
    if (i < NN) g_cnt[i] = 0;
}
__global__ void count_kernel(const int* __restrict__ nodes) {
    int i = blockIdx.x*blockDim.x + threadIdx.x;
    if (i < MROWS) atomicAdd(&g_cnt[nodes[i]], 1);
}
__global__ void inv_kernel() {
    int i = blockIdx.x*blockDim.x + threadIdx.x;
    if (i < NN) g_inv[i] = 1.f / (float)max(g_cnt[i], 1);
}

// ---------------- pipelined split-bf16 mma GEMM ----------------
// MODE 0: C = A@W + bias -> fp32 Cout + packed Cp
// MODE 1: C = relu(A@W + bias) -> packed Cp only
// MODE 2: init: A = xp[aidx[row]]; epilogue adds lp*v + root + bias0 -> fp32 Cout
// MODE 3: mp2, K=256: kt<4 A=z2p dense, kt>=4 A=xaggp gathered; relu -> fp32 Cout

template<int MODE>
__global__ void __launch_bounds__(256, 2)
mma2_gemm(const unsigned* __restrict__ Apk, const unsigned* __restrict__ blob,
          float* __restrict__ Cout, unsigned* __restrict__ Cp,
          const float* __restrict__ bias, const int* __restrict__ aidx,
          const unsigned* __restrict__ A2pk, const float* __restrict__ logp,
          const int* __restrict__ rootl)
{
    extern __shared__ __align__(16) unsigned sm[];
    constexpr int NB = (MODE == 3) ? 2 : 1;
    constexpr int KT = (MODE == 3) ? 8 : 4;

    const int tid = threadIdx.x;
    const int lane = tid & 31, warp = tid >> 5;
    const int wm = warp & 3, wn = warp >> 2;     // warp tile: 32(m) x 64(n)
    const int brow = blockIdx.x * 128;

    const unsigned bBase = smem_u32(sm);
    const unsigned aBase = bBase + NB*BHALF;
    const float* bp = (MODE == 2) ? (const float*)g_bias0 : bias;

    float c[2][8][4];
    #pragma unroll
    for (int i = 0; i < 2; i++)
        #pragma unroll
        for (int j = 0; j < 8; j++)
            #pragma unroll
            for (int q = 0; q < 4; q++) c[i][j][q] = 0.f;

    // ---- issue B load (resident for whole CTA) ----
    #pragma unroll
    for (int it = 0; it < NB*16; it++) {
        int ch = tid + it*256;
        int r = ch >> 5, q = ch & 31;
        CP16(bBase + r*BROWB + q*16, blob + (size_t)r*128 + q*4);
    }
    CPCOMMIT();

    // ---- A slice loader (32 real k per kt, 16KB) ----
    auto loadA = [&](int kt) {
        unsigned dstB = aBase + (kt & 1)*ABUF;
        #pragma unroll
        for (int it = 0; it < 4; it++) {
            int ch = tid + it*256;
            int r = ch >> 3, q = ch & 7;
            int gr = brow + r;
            const unsigned* src;
            if (MODE == 2) {
                src = Apk + (size_t)aidx[gr]*HH + kt*32 + q*4;
            } else if (MODE == 3) {
                src = (kt < 4) ? Apk  + (size_t)gr*HH + kt*32 + q*4
                               : A2pk + (size_t)aidx[gr]*HH + (kt-4)*32 + q*4;
            } else {
                src = Apk + (size_t)gr*HH + kt*32 + q*4;
            }
            CP16(dstB + r*AROWB + q*16, src);
        }
    };
    loadA(0);
    CPCOMMIT();

    // ---- ldmatrix addresses ----
    unsigned a_addr[2], b_addr[4];
    #pragma unroll
    for (int mf = 0; mf < 2; mf++) {
        int row = wm*32 + mf*16 + (lane & 15);
        a_addr[mf] = aBase + row*AROWB + (lane>>4)*16;
    }
    #pragma unroll
    for (int g = 0; g < 4; g++) {
        int row = wn*64 + g*16 + ((lane>>3)&1)*8 + (lane&7);
        b_addr[g] = bBase + row*BROWB + (lane>>4)*16;
    }

    // ---- main loop ----
    for (int kt = 0; kt < KT; kt++) {
        if (kt + 1 < KT) { loadA(kt + 1); CPCOMMIT(); CPWAIT(1); }
        else             { CPWAIT(0); }
        __syncthreads();

        const unsigned aoff = (kt & 1)*ABUF;
        const unsigned boff = (MODE == 3 && kt >= 4) ? (unsigned)BHALF : 0u;
        const int kb = (MODE == 3) ? (kt & 3) : kt;

        #pragma unroll
        for (int ks = 0; ks < 4; ks++) {
            const unsigned ko = (kb*4 + ks)*32;
            unsigned a0[4], a1[4], a0s[4], a1s[4];
            LDSM4(a0[0],a0[1],a0[2],a0[3], a_addr[0] + aoff + ks*32);
            LDSM4(a1[0],a1[1],a1[2],a1[3], a_addr[1] + aoff + ks*32);
            #pragma unroll
            for (int i = 0; i < 4; i++) {
                a0s[i] = __byte_perm(a0[i], 0, 0x1032);
                a1s[i] = __byte_perm(a1[i], 0, 0x1032);
            }
            #pragma unroll
            for (int g = 0; g < 4; g++) {
                unsigned b[4];
                LDSM4(b[0],b[1],b[2],b[3], b_addr[g] + boff + ko);
                MMA_BF16(c[0][2*g+0], a0[0],a0[1],a0[2],a0[3], b[0],b[2]);
                MMA_BF16(c[0][2*g+0], a0s[0],a0s[1],a0s[2],a0s[3], b[0],b[2]);
                MMA_BF16(c[0][2*g+1], a0[0],a0[1],a0[2],a0[3], b[1],b[3]);
                MMA_BF16(c[0][2*g+1], a0s[0],a0s[1],a0s[2],a0s[3], b[1],b[3]);
                MMA_BF16(c[1][2*g+0], a1[0],a1[1],a1[2],a1[3], b[0],b[2]);
                MMA_BF16(c[1][2*g+0], a1s[0],a1s[1],a1s[2],a1s[3], b[0],b[2]);
                MMA_BF16(c[1][2*g+1], a1[0],a1[1],a1[2],a1[3], b[1],b[3]);
                MMA_BF16(c[1][2*g+1], a1s[0],a1s[1],a1s[2],a1s[3], b[1],b[3]);
            }
        }
        __syncthreads();
    }

    // ---- epilogue ----
    const int gid = lane >> 2, tig = lane & 3;
    #pragma unroll
    for (int mf = 0; mf < 2; mf++) {
        #pragma unroll
        for (int half = 0; half < 2; half++) {
            int m = wm*32 + mf*16 + half*8 + gid;
            int gr = brow + m;
            float lp = 0.f; int isr = 0;
            if (MODE == 2) {
                int sub = gr >> 6;
                lp = logp[sub];
                isr = ((gr & 63) == rootl[sub]) ? 1 : 0;
            }
            #pragma unroll
            for (int nf = 0; nf < 8; nf++) {
                int n0 = wn*64 + nf*8 + tig*2;
                float v0 = c[mf][nf][half*2+0] + bp[n0];
                float v1 = c[mf][nf][half*2+1] + bp[n0+1];
                if (MODE == 2) {
                    v0 += lp * g_vlogp[n0]   + g_root[isr*HH + n0];
                    v1 += lp * g_vlogp[n0+1] + g_root[isr*HH + n0+1];
                }
                if (MODE == 1 || MODE == 3) { v0 = fmaxf(v0, 0.f); v1 = fmaxf(v1, 0.f); }
                if (MODE == 0 || MODE == 2 || MODE == 3) {
                    float2 o; o.x = v0; o.y = v1;
                    *(float2*)(Cout + (size_t)gr*HH + n0) = o;
                }
                if (MODE == 0 || MODE == 1) {
                    uint2 p; p.x = pack_a(v0); p.y = pack_a(v1);
                    *(uint2*)(Cp + (size_t)gr*HH + n0) = p;
                }
            }
        }
    }
}

// ---------------- per-subgraph edge aggregation (GIN input) ----------------
__global__ void agg_kernel(const float* __restrict__ h, unsigned* __restrict__ zp,
                           const int* __restrict__ esrc, const int* __restrict__ edst,
                           const int* __restrict__ eptr, const float* __restrict__ geps,
                           int l)
{
    __shared__ float acc[KK][HH];
    __shared__ int se[256], de[256];
    const int s = blockIdx.x;
    const int tid = threadIdx.x;    // 128, one per column
    const float eps1 = 1.f + geps[l];
    const size_t base = (size_t)s * KK;

    #pragma unroll 4
    for (int r = 0; r < KK; r++)
        acc[r][tid] = eps1 * h[(base + r)*HH + tid];
    __syncthreads();

    const int e0 = eptr[s], e1 = eptr[s+1];
    for (int eb = e0; eb < e1; eb += 256) {
        int ne = min(256, e1 - eb);
        for (int i = tid; i < ne; i += 128) {
            se[i] = esrc[eb + i];
            de[i] = edst[eb + i];
        }
        __syncthreads();
        for (int i = 0; i < ne; i++)
            acc[de[i]][tid] += __ldg(&h[(base + se[i])*HH + tid]);
        __syncthreads();
    }

    #pragma unroll 4
    for (int r = 0; r < KK; r++)
        zp[(base + r)*HH + tid] = pack_a(acc[r][tid]);
}

// ---------------- scatter-mean pieces ----------------
__global__ void zero_xagg_kernel() {
    int i = blockIdx.x*blockDim.x + threadIdx.x;   // covers NN*HH exactly
    g_xagg[i] = 0.f;
    if (i < 2*HH) g_stats[i] = 0.f;
}
__global__ void scatter_kernel(const float* __restrict__ z, const int* __restrict__ nodes) {
    int idx = blockIdx.x*blockDim.x + threadIdx.x;  // covers MROWS*HH exactly
    int row = idx >> 7, c = idx & 127;
    atomicAdd(&g_xagg[(size_t)nodes[row]*HH + c], z[idx]);
}
__global__ void pack_xagg_kernel() {
    int idx = blockIdx.x*256 + threadIdx.x;   // covers NN*HH exactly
    int row = idx >> 7;
    g_xaggp[idx] = pack_a(g_xagg[idx] * g_inv[row]);
}

// ---------------- batchnorm ----------------
__global__ void bn_reduce_kernel(const float* __restrict__ u) {
    int c = threadIdx.x;
    float s = 0.f, ss = 0.f;
    for (int r = blockIdx.x; r < MROWS; r += gridDim.x) {
        float v = u[(size_t)r*HH + c];
        s += v; ss += v*v;
    }
    atomicAdd(&g_stats[c], s);
    atomicAdd(&g_stats[HH + c], ss);
}
__global__ void bn_apply_kernel(const float* __restrict__ u, float* __restrict__ h,
                                const float* __restrict__ gamma, const float* __restrict__ beta) {
    int idx = blockIdx.x*blockDim.x + threadIdx.x;
    int c = idx & 127;
    const float invM = 1.f / (float)MROWS;
    float mu  = g_stats[c] * invM;
    float var = g_stats[HH + c] * invM - mu*mu;
    float g = gamma[c] * rsqrtf(var + 1e-5f);
    h[idx] = (u[idx] - mu) * g + beta[c] + h[idx];
}

// ---------------- launch ----------------
extern "C" void kernel_launch(void* const* d_in, const int* in_sizes, int n_in,
                              void* d_out, int out_size) {
    const float* x    = (const float*)d_in[0];
    const float* logp = (const float*)d_in[1];
    const float* npw  = (const float*)d_in[2];
    const float* npb  = (const float*)d_in[3];
    const float* lpw  = (const float*)d_in[4];
    const float* lpb  = (const float*)d_in[5];
    const float* remb = (const float*)d_in[6];
    const float* ipw  = (const float*)d_in[7];
    const float* ipb  = (const float*)d_in[8];
    const float* geps = (const float*)d_in[9];
    const float* w1   = (const float*)d_in[10];
    const float* b1   = (const float*)d_in[11];
    const float* w2   = (const float*)d_in[12];
    const float* b2   = (const float*)d_in[13];
    const float* mp2w = (const float*)d_in[14];
    const float* mp2b = (const float*)d_in[15];
    const float* bng  = (const float*)d_in[16];
    const float* bnb  = (const float*)d_in[17];
    const int* nodes  = (const int*)d_in[18];
    const int* rootl  = (const int*)d_in[19];
    const int* eidx   = (const int*)d_in[20];
    const int* eptr   = (const int*)d_in[21];
    float* hout = (float*)d_out;

    float *p_z2, *p_u;
    unsigned *p_xp, *p_zp, *p_tp, *p_z2p, *p_xaggp, *p_Mbp, *p_w1bp, *p_w2bp, *p_mp2bp;
    cudaGetSymbolAddress((void**)&p_z2, g_z2);
    cudaGetSymbolAddress((void**)&p_u, g_u);
    cudaGetSymbolAddress((void**)&p_xp, g_xp);
    cudaGetSymbolAddress((void**)&p_zp, g_zp);
    cudaGetSymbolAddress((void**)&p_tp, g_tp);
    cudaGetSymbolAddress((void**)&p_z2p, g_z2p);
    cudaGetSymbolAddress((void**)&p_xaggp, g_xaggp);
    cudaGetSymbolAddress((void**)&p_Mbp, g_Mbp);
    cudaGetSymbolAddress((void**)&p_w1bp, g_w1bp);
    cudaGetSymbolAddress((void**)&p_w2bp, g_w2bp);
    cudaGetSymbolAddress((void**)&p_mp2bp, g_mp2bp);

    const int SM1 = BHALF + 2*ABUF;        // 104448
    const int SM3 = 2*BHALF + 2*ABUF;      // 172032
    cudaFuncSetAttribute(mma2_gemm<0>, cudaFuncAttributeMaxDynamicSharedMemorySize, SM1);
    cudaFuncSetAttribute(mma2_gemm<1>, cudaFuncAttributeMaxDynamicSharedMemorySize, SM1);
    cudaFuncSetAttribute(mma2_gemm<2>, cudaFuncAttributeMaxDynamicSharedMemorySize, SM1);
    cudaFuncSetAttribute(mma2_gemm<3>, cudaFuncAttributeMaxDynamicSharedMemorySize, SM3);

    const int* esrc = eidx;
    const int* edst = eidx + EE;

    // ---- prologue: pack x, fold + pack weights, node counts ----
    pack_x_kernel<<<(NN*HH)/256, 256>>>(x);
    fold_M_kernel<<<128, 128>>>(npw, ipw);
    fold_vec_kernel<<<1, 128>>>(lpw, npb, lpb, remb, ipw, ipb);
    pack_w128<<<dim3(64, LL), 256>>>(w1, p_w1bp);
    pack_w128<<<dim3(64, LL), 256>>>(w2, p_w2bp);
    pack_w256<<<dim3(128, LL), 256>>>(mp2w, p_mp2bp);
    zero_cnt_kernel<<<(NN + 255)/256, 256>>>();
    count_kernel<<<MROWS/256, 256>>>(nodes);
    inv_kernel<<<(NN + 255)/256, 256>>>();

    // ---- init: h = gather(x)@M + lp*v + root + bias ----
    mma2_gemm<2><<<MROWS/128, 256, SM1>>>(p_xp, p_Mbp, hout, nullptr, nullptr,
                                          nodes, nullptr, logp, rootl);

    // ---- layers ----
    for (int l = 0; l < LL; l++) {
        agg_kernel<<<SS, 128>>>(hout, p_zp, esrc, edst, eptr, geps, l);

        mma2_gemm<1><<<MROWS/128, 256, SM1>>>(p_zp, p_w1bp + (size_t)l*16384,
                                              nullptr, p_tp, b1 + l*HH,
                                              nullptr, nullptr, nullptr, nullptr);
        mma2_gemm<0><<<MROWS/128, 256, SM1>>>(p_tp, p_w2bp + (size_t)l*16384,
                                              p_z2, p_z2p, b2 + l*HH,
                                              nullptr, nullptr, nullptr, nullptr);

        zero_xagg_kernel<<<(NN*HH)/256, 256>>>();
        scatter_kernel<<<(MROWS*HH)/256, 256>>>(p_z2, nodes);
        pack_xagg_kernel<<<(NN*HH)/256, 256>>>();

        mma2_gemm<3><<<MROWS/128, 256, SM3>>>(p_z2p, p_mp2bp + (size_t)l*32768,
                                              p_u, nullptr, mp2b + l*HH,
                                              nodes, p_xaggp, nullptr, nullptr);

        bn_reduce_kernel<<<512, 128>>>(p_u);
        bn_apply_kernel<<<(MROWS*HH)/256, 256>>>(p_u, hout, bng + l*HH, bnb + l*HH);
    }
}

// round 6
// speedup vs baseline: 1.3799x; 1.3799x over previous
#include <cuda_runtime.h>
#include <cuda_bf16.h>

#define NN     50000
#define SS     2048
#define KK     64
#define HH     128
#define EE     524288
#define LL     5
#define MROWS  (SS*KK)      // 131072

// ---------------- scratch (device globals; no allocations) ----------------
__device__ unsigned g_Mbp[HH*HH];          // folded init weight, (bh|bl<<16), [n][k]
__device__ unsigned g_w1bp[LL*HH*HH];
__device__ unsigned g_w2bp[LL*HH*HH];
__device__ unsigned g_mp2bp[LL*2*HH*HH];   // [l][half][n][k_local]
__device__ float    g_vlogp[HH];
__device__ float    g_bias0[HH];
__device__ float    g_root[2*HH];
__device__ unsigned g_xp[NN*HH];           // packed x
__device__ unsigned g_zp[MROWS*HH];        // packed agg output
__device__ unsigned g_tp[MROWS*HH];        // packed t
__device__ unsigned g_z2p[MROWS*HH];       // packed z2 (for mp2)
__device__ float    g_u[MROWS*HH];
__device__ float    g_xagg[NN*HH];
__device__ unsigned g_xaggp[NN*HH];        // packed xagg*inv
__device__ float    g_inv[NN];
__device__ int      g_cnt[NN];
__device__ float    g_stats[2*HH];

// ---------------- helpers ----------------
__device__ __forceinline__ unsigned pack_a(float v) {
    __nv_bfloat16 hi = __float2bfloat16_rn(v);
    __nv_bfloat16 lo = __float2bfloat16_rn(v - __bfloat162float(hi));
    return (unsigned)__bfloat16_as_ushort(hi)
         | ((unsigned)__bfloat16_as_ushort(lo) << 16);
}
__device__ __forceinline__ unsigned smem_u32(const void* p) {
    unsigned a;
    asm("{ .reg .u64 t; cvta.to.shared.u64 t, %1; cvt.u32.u64 %0, t; }" : "=r"(a) : "l"(p));
    return a;
}

#define CP16(dst, src) \
    asm volatile("cp.async.cg.shared.global [%0], [%1], 16;" :: "r"(dst), "l"(src) : "memory")
#define CPCOMMIT() asm volatile("cp.async.commit_group;" ::: "memory")
#define CPWAIT(n)  asm volatile("cp.async.wait_group %0;" :: "n"(n) : "memory")

#define LDSM4(R0,R1,R2,R3,ADDR) \
    asm volatile("ldmatrix.sync.aligned.m8n8.x4.shared.b16 {%0,%1,%2,%3}, [%4];" \
        : "=r"(R0),"=r"(R1),"=r"(R2),"=r"(R3) : "r"(ADDR))

#define MMA_BF16(C, A0,A1,A2,A3, B0,B1) \
    asm volatile("mma.sync.aligned.m16n8k16.row.col.f32.bf16.bf16.f32 " \
        "{%0,%1,%2,%3},{%4,%5,%6,%7},{%8,%9},{%0,%1,%2,%3};" \
        : "+f"(C[0]),"+f"(C[1]),"+f"(C[2]),"+f"(C[3]) \
        : "r"(A0),"r"(A1),"r"(A2),"r"(A3),"r"(B0),"r"(B1))

// smem geometry
#define BROWB  528
#define AROWB  144
#define BHALF  (128*BROWB)      // 67584
#define ABUF   (128*AROWB)      // 18432

// ---------------- weight folding / packing ----------------
__global__ void pack_x_kernel(const float* __restrict__ x) {
    int idx = blockIdx.x*256 + threadIdx.x;
    g_xp[idx] = pack_a(x[idx]);
}
__global__ void fold_M_kernel(const float* __restrict__ npw, const float* __restrict__ ipw) {
    int k = blockIdx.x, n = threadIdx.x;
    float s = 0.f;
    for (int c = 0; c < HH; c++) s += npw[k*HH + c] * ipw[c*HH + n];
    g_Mbp[n*HH + k] = pack_a(s);
}
__global__ void fold_vec_kernel(const float* __restrict__ lpw, const float* __restrict__ npb,
                                const float* __restrict__ lpb, const float* __restrict__ remb,
                                const float* __restrict__ ipw, const float* __restrict__ ipb) {
    int j = threadIdx.x;
    float v = 0.f, b = ipb[j], r0 = 0.f, r1 = 0.f;
    for (int k = 0; k < HH; k++) {
        float wa = ipw[k*HH + j];
        float wb = ipw[(HH + k)*HH + j];
        float wc = ipw[(2*HH + k)*HH + j];
        v  += lpw[k] * wb;
        b  += npb[k] * wa + lpb[k] * wb;
        r0 += remb[k] * wc;
        r1 += remb[HH + k] * wc;
    }
    g_vlogp[j] = v; g_bias0[j] = b; g_root[j] = r0; g_root[HH + j] = r1;
}
__global__ void pack_w128(const float* __restrict__ W, unsigned* __restrict__ out) {
    int l = blockIdx.y;
    int idx = blockIdx.x*256 + threadIdx.x;
    int k = idx >> 7, n = idx & 127;
    out[(size_t)l*16384 + n*128 + k] = pack_a(W[(size_t)l*16384 + idx]);
}
__global__ void pack_w256(const float* __restrict__ W, unsigned* __restrict__ out) {
    int l = blockIdx.y;
    int idx = blockIdx.x*256 + threadIdx.x;
    int kg = idx >> 7, n = idx & 127;
    int h = kg >> 7, kl = kg & 127;
    out[(size_t)l*32768 + h*16384 + n*128 + kl] = pack_a(W[(size_t)l*32768 + idx]);
}

// ---------------- counts for scatter-mean ----------------
__global__ void zero_cnt_kernel() {
    int i = blockIdx.x*blockDim.x + threadIdx.x;
    if (i < NN) g_cnt[i] = 0;
}
__global__ void count_kernel(const int* __restrict__ nodes) {
    int i = blockIdx.x*blockDim.x + threadIdx.x;
    if (i < MROWS) atomicAdd(&g_cnt[nodes[i]], 1);
}
__global__ void inv_kernel() {
    int i = blockIdx.x*blockDim.x + threadIdx.x;
    if (i < NN) g_inv[i] = 1.f / (float)max(g_cnt[i], 1);
}
__global__ void zero_xagg_kernel() {
    int i = blockIdx.x*blockDim.x + threadIdx.x;
    g_xagg[i] = 0.f;
    if (i < 2*HH) g_stats[i] = 0.f;
}
__global__ void pack_xagg_kernel() {
    int idx = blockIdx.x*256 + threadIdx.x;
    int row = idx >> 7;
    g_xaggp[idx] = pack_a(g_xagg[idx] * g_inv[row]);
}

// ---------------- pipelined split-bf16 mma GEMM ----------------
// MODE 0: z2 = A@W + bias -> packed z2p + fused scatter atomics to g_xagg
// MODE 1: C = relu(A@W + bias) -> packed Cp
// MODE 2: init: A = xp[aidx]; epilogue adds lp*v + root + bias0 -> fp32 Cout
// MODE 3: mp2, K=256: kt<4 A dense, kt>=4 A2 gathered; relu -> fp32 Cout + fused bn stats

template<int MODE>
__global__ void __launch_bounds__(256, 2)
mma2_gemm(const unsigned* __restrict__ Apk, const unsigned* __restrict__ blob,
          float* __restrict__ Cout, unsigned* __restrict__ Cp,
          const float* __restrict__ bias, const int* __restrict__ aidx,
          const unsigned* __restrict__ A2pk, const float* __restrict__ logp,
          const int* __restrict__ rootl)
{
    extern __shared__ __align__(16) unsigned sm[];
    constexpr int NB = (MODE == 3) ? 2 : 1;
    constexpr int KT = (MODE == 3) ? 8 : 4;

    const int tid = threadIdx.x;
    const int lane = tid & 31, warp = tid >> 5;
    const int wm = warp & 3, wn = warp >> 2;     // warp tile: 32(m) x 64(n)
    const int brow = blockIdx.x * 128;

    const unsigned bBase = smem_u32(sm);
    const unsigned aBase = bBase + NB*BHALF;
    const float* bp = (MODE == 2) ? (const float*)g_bias0 : bias;

    float c[2][8][4];
    #pragma unroll
    for (int i = 0; i < 2; i++)
        #pragma unroll
        for (int j = 0; j < 8; j++)
            #pragma unroll
            for (int q = 0; q < 4; q++) c[i][j][q] = 0.f;

    // ---- B load (resident whole CTA) ----
    #pragma unroll
    for (int it = 0; it < NB*16; it++) {
        int ch = tid + it*256;
        int r = ch >> 5, q = ch & 31;
        CP16(bBase + r*BROWB + q*16, blob + (size_t)r*128 + q*4);
    }
    CPCOMMIT();

    auto loadA = [&](int kt) {
        unsigned dstB = aBase + (kt & 1)*ABUF;
        #pragma unroll
        for (int it = 0; it < 4; it++) {
            int ch = tid + it*256;
            int r = ch >> 3, q = ch & 7;
            int gr = brow + r;
            const unsigned* src;
            if (MODE == 2) {
                src = Apk + (size_t)aidx[gr]*HH + kt*32 + q*4;
            } else if (MODE == 3) {
                src = (kt < 4) ? Apk  + (size_t)gr*HH + kt*32 + q*4
                               : A2pk + (size_t)aidx[gr]*HH + (kt-4)*32 + q*4;
            } else {
                src = Apk + (size_t)gr*HH + kt*32 + q*4;
            }
            CP16(dstB + r*AROWB + q*16, src);
        }
    };
    loadA(0);
    CPCOMMIT();

    unsigned a_addr[2], b_addr[4];
    #pragma unroll
    for (int mf = 0; mf < 2; mf++) {
        int row = wm*32 + mf*16 + (lane & 15);
        a_addr[mf] = aBase + row*AROWB + (lane>>4)*16;
    }
    #pragma unroll
    for (int g = 0; g < 4; g++) {
        int row = wn*64 + g*16 + ((lane>>3)&1)*8 + (lane&7);
        b_addr[g] = bBase + row*BROWB + (lane>>4)*16;
    }

    for (int kt = 0; kt < KT; kt++) {
        if (kt + 1 < KT) { loadA(kt + 1); CPCOMMIT(); CPWAIT(1); }
        else             { CPWAIT(0); }
        __syncthreads();

        const unsigned aoff = (kt & 1)*ABUF;
        const unsigned boff = (MODE == 3 && kt >= 4) ? (unsigned)BHALF : 0u;
        const int kb = (MODE == 3) ? (kt & 3) : kt;

        #pragma unroll
        for (int ks = 0; ks < 4; ks++) {
            const unsigned ko = (kb*4 + ks)*32;
            unsigned a0[4], a1[4], a0s[4], a1s[4], bb[4][4];
            LDSM4(a0[0],a0[1],a0[2],a0[3], a_addr[0] + aoff + ks*32);
            LDSM4(a1[0],a1[1],a1[2],a1[3], a_addr[1] + aoff + ks*32);
            #pragma unroll
            for (int i = 0; i < 4; i++) {
                a0s[i] = __byte_perm(a0[i], 0, 0x1032);
                a1s[i] = __byte_perm(a1[i], 0, 0x1032);
            }
            #pragma unroll
            for (int g = 0; g < 4; g++)
                LDSM4(bb[g][0],bb[g][1],bb[g][2],bb[g][3], b_addr[g] + boff + ko);
            // term 1: 16 independent MMAs (distinct accumulators)
            #pragma unroll
            for (int g = 0; g < 4; g++) {
                MMA_BF16(c[0][2*g+0], a0[0],a0[1],a0[2],a0[3], bb[g][0],bb[g][2]);
                MMA_BF16(c[0][2*g+1], a0[0],a0[1],a0[2],a0[3], bb[g][1],bb[g][3]);
                MMA_BF16(c[1][2*g+0], a1[0],a1[1],a1[2],a1[3], bb[g][0],bb[g][2]);
                MMA_BF16(c[1][2*g+1], a1[0],a1[1],a1[2],a1[3], bb[g][1],bb[g][3]);
            }
            // term 2: swapped A (cross terms), again 16 independent
            #pragma unroll
            for (int g = 0; g < 4; g++) {
                MMA_BF16(c[0][2*g+0], a0s[0],a0s[1],a0s[2],a0s[3], bb[g][0],bb[g][2]);
                MMA_BF16(c[0][2*g+1], a0s[0],a0s[1],a0s[2],a0s[3], bb[g][1],bb[g][3]);
                MMA_BF16(c[1][2*g+0], a1s[0],a1s[1],a1s[2],a1s[3], bb[g][0],bb[g][2]);
                MMA_BF16(c[1][2*g+1], a1s[0],a1s[1],a1s[2],a1s[3], bb[g][1],bb[g][3]);
            }
        }
        __syncthreads();
    }

    // ---- epilogue ----
    const int gid = lane >> 2, tig = lane & 3;
    float s0[8], s1[8], q0[8], q1[8];     // MODE 3 column stats
    if (MODE == 3) {
        #pragma unroll
        for (int nf = 0; nf < 8; nf++) { s0[nf]=0.f; s1[nf]=0.f; q0[nf]=0.f; q1[nf]=0.f; }
    }
    #pragma unroll
    for (int mf = 0; mf < 2; mf++) {
        #pragma unroll
        for (int half = 0; half < 2; half++) {
            int m = wm*32 + mf*16 + half*8 + gid;
            int gr = brow + m;
            float lp = 0.f; int isr = 0, nd = 0;
            if (MODE == 2) {
                int sub = gr >> 6;
                lp = logp[sub];
                isr = ((gr & 63) == rootl[sub]) ? 1 : 0;
            }
            if (MODE == 0) nd = aidx[gr];
            #pragma unroll
            for (int nf = 0; nf < 8; nf++) {
                int n0 = wn*64 + nf*8 + tig*2;
                float v0 = c[mf][nf][half*2+0] + bp[n0];
                float v1 = c[mf][nf][half*2+1] + bp[n0+1];
                if (MODE == 2) {
                    v0 += lp * g_vlogp[n0]   + g_root[isr*HH + n0];
                    v1 += lp * g_vlogp[n0+1] + g_root[isr*HH + n0+1];
                }
                if (MODE == 1 || MODE == 3) { v0 = fmaxf(v0, 0.f); v1 = fmaxf(v1, 0.f); }
                if (MODE == 2 || MODE == 3) {
                    float2 o; o.x = v0; o.y = v1;
                    *(float2*)(Cout + (size_t)gr*HH + n0) = o;
                }
                if (MODE == 0 || MODE == 1) {
                    uint2 p; p.x = pack_a(v0); p.y = pack_a(v1);
                    *(uint2*)(Cp + (size_t)gr*HH + n0) = p;
                }
                if (MODE == 0) {
                    atomicAdd(&g_xagg[(size_t)nd*HH + n0],     v0);
                    atomicAdd(&g_xagg[(size_t)nd*HH + n0 + 1], v1);
                }
                if (MODE == 3) {
                    s0[nf] += v0; s1[nf] += v1;
                    q0[nf] += v0*v0; q1[nf] += v1*v1;
                }
            }
        }
    }
    if (MODE == 3) {
        // reduce over gid (lanes differing by 4,8,16), then lanes 0..3 do atomics
        #pragma unroll
        for (int nf = 0; nf < 8; nf++) {
            #pragma unroll
            for (int off = 4; off < 32; off <<= 1) {
                s0[nf] += __shfl_xor_sync(0xFFFFFFFFu, s0[nf], off);
                s1[nf] += __shfl_xor_sync(0xFFFFFFFFu, s1[nf], off);
                q0[nf] += __shfl_xor_sync(0xFFFFFFFFu, q0[nf], off);
                q1[nf] += __shfl_xor_sync(0xFFFFFFFFu, q1[nf], off);
            }
        }
        if (gid == 0) {
            #pragma unroll
            for (int nf = 0; nf < 8; nf++) {
                int n0 = wn*64 + nf*8 + tig*2;
                atomicAdd(&g_stats[n0],        s0[nf]);
                atomicAdd(&g_stats[n0+1],      s1[nf]);
                atomicAdd(&g_stats[HH+n0],     q0[nf]);
                atomicAdd(&g_stats[HH+n0+1],   q1[nf]);
            }
        }
    }
}

// ---------------- agg (optionally fused with previous layer's BN) ----------------
// FUSE_BN==0: acc = (1+eps)*H[row]; edges from smem copy of H
// FUSE_BN==1: hn = bn(u)*gamma+beta + H; H = hn; acc = (1+eps)*hn
template<int FUSE_BN>
__global__ void __launch_bounds__(128)
agg_kernel(const float* __restrict__ u, float* __restrict__ H,
           unsigned* __restrict__ zp,
           const int* __restrict__ esrc, const int* __restrict__ edst,
           const int* __restrict__ eptr, const float* __restrict__ geps,
           const float* __restrict__ gamma, const float* __restrict__ beta,
           int l)
{
    extern __shared__ float fsm[];
    float* hsm = fsm;              // [KK][HH]
    float* acc = fsm + KK*HH;      // [KK][HH]
    __shared__ int se[256], de[256];
    const int s = blockIdx.x;
    const int tid = threadIdx.x;    // 128, one per column
    const float eps1 = 1.f + geps[l];
    const size_t base = (size_t)s * KK;

    float g = 0.f, bt = 0.f, mu = 0.f;
    if (FUSE_BN) {
        const float invM = 1.f / (float)MROWS;
        mu = g_stats[tid] * invM;
        float var = g_stats[HH + tid] * invM - mu*mu;
        g = gamma[tid] * rsqrtf(var + 1e-5f);
        bt = beta[tid];
    }

    #pragma unroll 4
    for (int r = 0; r < KK; r++) {
        float hv;
        if (FUSE_BN) {
            float uv = u[(base + r)*HH + tid];
            hv = (uv - mu) * g + bt + H[(base + r)*HH + tid];
            H[(base + r)*HH + tid] = hv;
        } else {
            hv = H[(base + r)*HH + tid];
        }
        hsm[r*HH + tid] = hv;
        acc[r*HH + tid] = eps1 * hv;
    }
    __syncthreads();

    const int e0 = eptr[s], e1 = eptr[s+1];
    for (int eb = e0; eb < e1; eb += 256) {
        int ne = min(256, e1 - eb);
        for (int i = tid; i < ne; i += 128) {
            se[i] = esrc[eb + i];
            de[i] = edst[eb + i];
        }
        __syncthreads();
        for (int i = 0; i < ne; i++)
            acc[de[i]*HH + tid] += hsm[se[i]*HH + tid];
        __syncthreads();
    }

    #pragma unroll 4
    for (int r = 0; r < KK; r++)
        zp[(base + r)*HH + tid] = pack_a(acc[r*HH + tid]);
}

// ---------------- final batchnorm apply ----------------
__global__ void bn_apply_kernel(const float* __restrict__ u, float* __restrict__ h,
                                const float* __restrict__ gamma, const float* __restrict__ beta) {
    int idx = blockIdx.x*blockDim.x + threadIdx.x;
    int c = idx & 127;
    const float invM = 1.f / (float)MROWS;
    float mu  = g_stats[c] * invM;
    float var = g_stats[HH + c] * invM - mu*mu;
    float g = gamma[c] * rsqrtf(var + 1e-5f);
    h[idx] = (u[idx] - mu) * g + beta[c] + h[idx];
}

// ---------------- launch ----------------
extern "C" void kernel_launch(void* const* d_in, const int* in_sizes, int n_in,
                              void* d_out, int out_size) {
    const float* x    = (const float*)d_in[0];
    const float* logp = (const float*)d_in[1];
    const float* npw  = (const float*)d_in[2];
    const float* npb  = (const float*)d_in[3];
    const float* lpw  = (const float*)d_in[4];
    const float* lpb  = (const float*)d_in[5];
    const float* remb = (const float*)d_in[6];
    const float* ipw  = (const float*)d_in[7];
    const float* ipb  = (const float*)d_in[8];
    const float* geps = (const float*)d_in[9];
    const float* w1   = (const float*)d_in[10];
    const float* b1   = (const float*)d_in[11];
    const float* w2   = (const float*)d_in[12];
    const float* b2   = (const float*)d_in[13];
    const float* mp2w = (const float*)d_in[14];
    const float* mp2b = (const float*)d_in[15];
    const float* bng  = (const float*)d_in[16];
    const float* bnb  = (const float*)d_in[17];
    const int* nodes  = (const int*)d_in[18];
    const int* rootl  = (const int*)d_in[19];
    const int* eidx   = (const int*)d_in[20];
    const int* eptr   = (const int*)d_in[21];
    float* hout = (float*)d_out;

    float *p_u;
    unsigned *p_xp, *p_zp, *p_tp, *p_z2p, *p_xaggp, *p_Mbp, *p_w1bp, *p_w2bp, *p_mp2bp;
    cudaGetSymbolAddress((void**)&p_u, g_u);
    cudaGetSymbolAddress((void**)&p_xp, g_xp);
    cudaGetSymbolAddress((void**)&p_zp, g_zp);
    cudaGetSymbolAddress((void**)&p_tp, g_tp);
    cudaGetSymbolAddress((void**)&p_z2p, g_z2p);
    cudaGetSymbolAddress((void**)&p_xaggp, g_xaggp);
    cudaGetSymbolAddress((void**)&p_Mbp, g_Mbp);
    cudaGetSymbolAddress((void**)&p_w1bp, g_w1bp);
    cudaGetSymbolAddress((void**)&p_w2bp, g_w2bp);
    cudaGetSymbolAddress((void**)&p_mp2bp, g_mp2bp);

    const int SM1 = BHALF + 2*ABUF;        // 104448
    const int SM3 = 2*BHALF + 2*ABUF;      // 172032
    const int SMA = 2*KK*HH*4;             // 65536 (agg)
    cudaFuncSetAttribute(mma2_gemm<0>, cudaFuncAttributeMaxDynamicSharedMemorySize, SM1);
    cudaFuncSetAttribute(mma2_gemm<1>, cudaFuncAttributeMaxDynamicSharedMemorySize, SM1);
    cudaFuncSetAttribute(mma2_gemm<2>, cudaFuncAttributeMaxDynamicSharedMemorySize, SM1);
    cudaFuncSetAttribute(mma2_gemm<3>, cudaFuncAttributeMaxDynamicSharedMemorySize, SM3);
    cudaFuncSetAttribute(agg_kernel<0>, cudaFuncAttributeMaxDynamicSharedMemorySize, SMA);
    cudaFuncSetAttribute(agg_kernel<1>, cudaFuncAttributeMaxDynamicSharedMemorySize, SMA);

    const int* esrc = eidx;
    const int* edst = eidx + EE;

    // ---- prologue ----
    pack_x_kernel<<<(NN*HH)/256, 256>>>(x);
    fold_M_kernel<<<128, 128>>>(npw, ipw);
    fold_vec_kernel<<<1, 128>>>(lpw, npb, lpb, remb, ipw, ipb);
    pack_w128<<<dim3(64, LL), 256>>>(w1, p_w1bp);
    pack_w128<<<dim3(64, LL), 256>>>(w2, p_w2bp);
    pack_w256<<<dim3(128, LL), 256>>>(mp2w, p_mp2bp);
    zero_cnt_kernel<<<(NN + 255)/256, 256>>>();
    count_kernel<<<MROWS/256, 256>>>(nodes);
    inv_kernel<<<(NN + 255)/256, 256>>>();

    // ---- init: h = gather(x)@M + lp*v + root + bias ----
    mma2_gemm<2><<<MROWS/128, 256, SM1>>>(p_xp, p_Mbp, hout, nullptr, nullptr,
                                          nodes, nullptr, logp, rootl);

    // ---- layers ----
    for (int l = 0; l < LL; l++) {
        if (l == 0)
            agg_kernel<0><<<SS, 128, SMA>>>(nullptr, hout, p_zp, esrc, edst, eptr,
                                            geps, nullptr, nullptr, l);
        else
            agg_kernel<1><<<SS, 128, SMA>>>(p_u, hout, p_zp, esrc, edst, eptr,
                                            geps, bng + (l-1)*HH, bnb + (l-1)*HH, l);

        zero_xagg_kernel<<<(NN*HH)/256, 256>>>();

        mma2_gemm<1><<<MROWS/128, 256, SM1>>>(p_zp, p_w1bp + (size_t)l*16384,
                                              nullptr, p_tp, b1 + l*HH,
                                              nullptr, nullptr, nullptr, nullptr);
        mma2_gemm<0><<<MROWS/128, 256, SM1>>>(p_tp, p_w2bp + (size_t)l*16384,
                                              nullptr, p_z2p, b2 + l*HH,
                                              nodes, nullptr, nullptr, nullptr);

        pack_xagg_kernel<<<(NN*HH)/256, 256>>>();

        mma2_gemm<3><<<MROWS/128, 256, SM3>>>(p_z2p, p_mp2bp + (size_t)l*32768,
                                              p_u, nullptr, mp2b + l*HH,
                                              nodes, p_xaggp, nullptr, nullptr);
    }

    // ---- final BN apply (layer L-1) ----
    bn_apply_kernel<<<(MROWS*HH)/256, 256>>>(p_u, hout, bng + (LL-1)*HH, bnb + (LL-1)*HH);
}

// round 7
// speedup vs baseline: 1.4495x; 1.0505x over previous
#include <cuda_runtime.h>
#include <cuda_bf16.h>

#define NN     50000
#define SS     2048
#define KK     64
#define HH     128
#define EE     524288
#define LL     5
#define MROWS  (SS*KK)      // 131072

typedef unsigned short u16;
typedef unsigned int   u32;

// ---------------- scratch (device globals; no allocations) ----------------
// weight blobs: per 128k block: [hi plane 16384 u16][lo plane 16384 u16], [n][k]
__device__ u16 g_Mb[2*16384];
__device__ u16 g_w1b[LL*2*16384];
__device__ u16 g_w2b[LL*2*16384];
__device__ u16 g_mp2b[LL*4*16384];     // [l][half][plane][n][k]
__device__ float g_vlogp[HH];
__device__ float g_bias0[HH];
__device__ float g_root[2*HH];
__device__ u16 g_xph[NN*HH],    g_xpl[NN*HH];
__device__ u16 g_zph[MROWS*HH], g_zpl[MROWS*HH];
__device__ u16 g_tph[MROWS*HH], g_tpl[MROWS*HH];
__device__ u16 g_z2h[MROWS*HH], g_z2l[MROWS*HH];
__device__ u16 g_xah[NN*HH],    g_xal[NN*HH];
__device__ float g_u[MROWS*HH];
__device__ float g_xagg[NN*HH];
__device__ float g_inv[NN];
__device__ int   g_cnt[NN];
__device__ float g_stats[2*HH];

// ---------------- helpers ----------------
__device__ __forceinline__ void splitf(float v, u16& h, u16& l) {
    __nv_bfloat16 hb = __float2bfloat16_rn(v);
    __nv_bfloat16 lb = __float2bfloat16_rn(v - __bfloat162float(hb));
    h = __bfloat16_as_ushort(hb);
    l = __bfloat16_as_ushort(lb);
}
__device__ __forceinline__ void pack2(float v0, float v1, u32& hi, u32& lo) {
    u16 h0, l0, h1, l1;
    splitf(v0, h0, l0); splitf(v1, h1, l1);
    hi = (u32)h0 | ((u32)h1 << 16);
    lo = (u32)l0 | ((u32)l1 << 16);
}
__device__ __forceinline__ u32 smem_u32(const void* p) {
    u32 a;
    asm("{ .reg .u64 t; cvta.to.shared.u64 t, %1; cvt.u32.u64 %0, t; }" : "=r"(a) : "l"(p));
    return a;
}

#define CP16(dst, src) \
    asm volatile("cp.async.cg.shared.global [%0], [%1], 16;" :: "r"(dst), "l"(src) : "memory")
#define CPCOMMIT() asm volatile("cp.async.commit_group;" ::: "memory")
#define CPWAIT(n)  asm volatile("cp.async.wait_group %0;" :: "n"(n) : "memory")

#define LDSM4(R0,R1,R2,R3,ADDR) \
    asm volatile("ldmatrix.sync.aligned.m8n8.x4.shared.b16 {%0,%1,%2,%3}, [%4];" \
        : "=r"(R0),"=r"(R1),"=r"(R2),"=r"(R3) : "r"(ADDR))

#define MMA_BF16(C, A0,A1,A2,A3, B0,B1) \
    asm volatile("mma.sync.aligned.m16n8k16.row.col.f32.bf16.bf16.f32 " \
        "{%0,%1,%2,%3},{%4,%5,%6,%7},{%8,%9},{%0,%1,%2,%3};" \
        : "+f"(C[0]),"+f"(C[1]),"+f"(C[2]),"+f"(C[3]) \
        : "r"(A0),"r"(A1),"r"(A2),"r"(A3),"r"(B0),"r"(B1))

// smem geometry (planar)
#define BROWB  272                 // 128 k * 2B + 16 pad
#define BPL    (128*BROWB)         // 34816 per B plane
#define AROWB  80                  // 32 k * 2B + 16 pad
#define APL    (128*AROWB)         // 10240 per A plane
#define ABUF2  (2*APL)             // hi+lo per kt buffer

// ---------------- packing kernels ----------------
__global__ void pack_x_kernel(const float* __restrict__ x) {
    int idx = blockIdx.x*256 + threadIdx.x;
    u16 h, l; splitf(x[idx], h, l);
    g_xph[idx] = h; g_xpl[idx] = l;
}
__global__ void fold_M_kernel(const float* __restrict__ npw, const float* __restrict__ ipw) {
    int k = blockIdx.x, n = threadIdx.x;
    float s = 0.f;
    for (int c = 0; c < HH; c++) s += npw[k*HH + c] * ipw[c*HH + n];
    u16 h, l; splitf(s, h, l);
    g_Mb[n*128 + k] = h; g_Mb[16384 + n*128 + k] = l;
}
__global__ void fold_vec_kernel(const float* __restrict__ lpw, const float* __restrict__ npb,
                                const float* __restrict__ lpb, const float* __restrict__ remb,
                                const float* __restrict__ ipw, const float* __restrict__ ipb) {
    int j = threadIdx.x;
    float v = 0.f, b = ipb[j], r0 = 0.f, r1 = 0.f;
    for (int k = 0; k < HH; k++) {
        float wa = ipw[k*HH + j];
        float wb = ipw[(HH + k)*HH + j];
        float wc = ipw[(2*HH + k)*HH + j];
        v  += lpw[k] * wb;
        b  += npb[k] * wa + lpb[k] * wb;
        r0 += remb[k] * wc;
        r1 += remb[HH + k] * wc;
    }
    g_vlogp[j] = v; g_bias0[j] = b; g_root[j] = r0; g_root[HH + j] = r1;
}
__global__ void pack_w128(const float* __restrict__ W, u16* __restrict__ out) {
    int l = blockIdx.y;
    int idx = blockIdx.x*256 + threadIdx.x;     // 0..16383
    int k = idx >> 7, n = idx & 127;
    u16 h, lo; splitf(W[(size_t)l*16384 + idx], h, lo);
    out[(size_t)l*32768 + n*128 + k] = h;
    out[(size_t)l*32768 + 16384 + n*128 + k] = lo;
}
__global__ void pack_w256(const float* __restrict__ W, u16* __restrict__ out) {
    int l = blockIdx.y;
    int idx = blockIdx.x*256 + threadIdx.x;     // 0..32767
    int kg = idx >> 7, n = idx & 127;
    int half = kg >> 7, kl = kg & 127;
    u16 h, lo; splitf(W[(size_t)l*32768 + idx], h, lo);
    out[(size_t)l*65536 + half*32768 + n*128 + kl] = h;
    out[(size_t)l*65536 + half*32768 + 16384 + n*128 + kl] = lo;
}

// ---------------- counts ----------------
__global__ void zero_cnt_kernel() {
    int i = blockIdx.x*blockDim.x + threadIdx.x;
    if (i < NN) g_cnt[i] = 0;
}
__global__ void count_kernel(const int* __restrict__ nodes) {
    int i = blockIdx.x*blockDim.x + threadIdx.x;
    if (i < MROWS) atomicAdd(&g_cnt[nodes[i]], 1);
}
__global__ void inv_kernel() {
    int i = blockIdx.x*blockDim.x + threadIdx.x;
    if (i < NN) g_inv[i] = 1.f / (float)max(g_cnt[i], 1);
}
__global__ void zero_xagg_kernel() {
    int i = blockIdx.x*blockDim.x + threadIdx.x;
    g_xagg[i] = 0.f;
    if (i < 2*HH) g_stats[i] = 0.f;
}
// pack xagg*inv to planes, zero xagg in place for next layer, zero stats
__global__ void pack_xagg_kernel() {
    int idx = blockIdx.x*256 + threadIdx.x;
    int row = idx >> 7;
    float v = g_xagg[idx] * g_inv[row];
    u16 h, l; splitf(v, h, l);
    g_xah[idx] = h; g_xal[idx] = l;
    g_xagg[idx] = 0.f;
    if (blockIdx.x == 0 && threadIdx.x < 2*HH) g_stats[threadIdx.x] = 0.f;
}

// ---------------- planar 3-term split-bf16 mma GEMM ----------------
// MODE 0: z2 = A@W + bias -> planes z2h/z2l + fused scatter atomics to g_xagg
// MODE 1: C = relu(A@W + bias) -> planes Cph/Cpl
// MODE 2: init: A = x[aidx]; epilogue adds lp*v + root + bias0 -> fp32 Cout
// MODE 3: mp2, K=256: kt<4 A dense, kt>=4 A2 gathered; relu -> fp32 Cout + bn stats

template<int MODE>
__global__ void __launch_bounds__(256, (MODE == 3) ? 1 : 2)
mma3_gemm(const u16* __restrict__ Ah, const u16* __restrict__ Al,
          const u16* __restrict__ blob,
          float* __restrict__ Cout, u16* __restrict__ Cph, u16* __restrict__ Cpl,
          const float* __restrict__ bias, const int* __restrict__ aidx,
          const u16* __restrict__ A2h, const u16* __restrict__ A2l,
          const float* __restrict__ logp, const int* __restrict__ rootl)
{
    extern __shared__ __align__(16) char sm[];
    constexpr int NP = (MODE == 3) ? 4 : 2;       // B planes
    constexpr int KT = (MODE == 3) ? 8 : 4;

    const int tid = threadIdx.x;
    const int lane = tid & 31, warp = tid >> 5;
    const int wm = warp & 3, wn = warp >> 2;       // warp tile: 32(m) x 64(n)
    const int brow = blockIdx.x * 128;

    const u32 bBase = smem_u32(sm);
    const u32 aBase = bBase + NP*BPL;
    const float* bp = (MODE == 2) ? (const float*)g_bias0 : bias;

    float c[2][8][4];
    #pragma unroll
    for (int i = 0; i < 2; i++)
        #pragma unroll
        for (int j = 0; j < 8; j++)
            #pragma unroll
            for (int q = 0; q < 4; q++) c[i][j][q] = 0.f;

    // ---- B planes load (resident) ----
    #pragma unroll
    for (int it = 0; it < NP*8; it++) {
        int ch = tid + it*256;                 // NP*2048 chunks of 16B
        int pl = ch >> 11, rem = ch & 2047;
        int r = rem >> 4, q = rem & 15;
        CP16(bBase + pl*BPL + r*BROWB + q*16, blob + (size_t)pl*16384 + r*128 + q*8);
    }
    CPCOMMIT();

    // ---- A slice loader (32 real k, hi+lo planes, 20KB) ----
    auto loadA = [&](int kt) {
        u32 dstB = aBase + (kt & 1)*ABUF2;
        #pragma unroll
        for (int it = 0; it < 4; it++) {
            int ch = tid + it*256;             // 1024 chunks
            int pl = ch >> 9, rem = ch & 511;
            int r = rem >> 2, q = rem & 3;
            int gr = brow + r;
            const u16 *sh, *sl;
            size_t rb;
            if (MODE == 2) {
                rb = (size_t)aidx[gr]*HH + kt*32 + q*8;
                sh = Ah; sl = Al;
            } else if (MODE == 3 && kt >= 4) {
                rb = (size_t)aidx[gr]*HH + (kt-4)*32 + q*8;
                sh = A2h; sl = A2l;
            } else {
                rb = (size_t)gr*HH + kt*32 + q*8;
                sh = Ah; sl = Al;
            }
            CP16(dstB + pl*APL + r*AROWB + q*16, (pl ? sl : sh) + rb);
        }
    };
    loadA(0);
    CPCOMMIT();

    // ---- ldmatrix addresses ----
    u32 a_addr[2], b_addr[4];
    #pragma unroll
    for (int mf = 0; mf < 2; mf++) {
        int row = wm*32 + mf*16 + (lane & 15);
        a_addr[mf] = aBase + row*AROWB + (lane>>4)*16;
    }
    #pragma unroll
    for (int g = 0; g < 4; g++) {
        int row = wn*64 + g*16 + ((lane>>3)&1)*8 + (lane&7);
        b_addr[g] = bBase + row*BROWB + (lane>>4)*16;
    }

    for (int kt = 0; kt < KT; kt++) {
        if (kt + 1 < KT) { loadA(kt + 1); CPCOMMIT(); CPWAIT(1); }
        else             { CPWAIT(0); }
        __syncthreads();

        const u32 aoff = (kt & 1)*ABUF2;
        const u32 bhoff = (MODE == 3 && kt >= 4) ? (u32)(2*BPL) : 0u;
        const int kb = (MODE == 3) ? (kt & 3) : kt;

        #pragma unroll
        for (int ks = 0; ks < 2; ks++) {       // each ks = 16 real k
            const u32 ko = (kb*2 + ks)*32;     // byte offset along k in B rows
            unsigned ah0[4], ah1[4], al0[4], al1[4], bb[4][4];
            LDSM4(ah0[0],ah0[1],ah0[2],ah0[3], a_addr[0] + aoff + ks*32);
            LDSM4(ah1[0],ah1[1],ah1[2],ah1[3], a_addr[1] + aoff + ks*32);
            LDSM4(al0[0],al0[1],al0[2],al0[3], a_addr[0] + aoff + APL + ks*32);
            LDSM4(al1[0],al1[1],al1[2],al1[3], a_addr[1] + aoff + APL + ks*32);
            // hi weight plane
            #pragma unroll
            for (int g = 0; g < 4; g++)
                LDSM4(bb[g][0],bb[g][1],bb[g][2],bb[g][3], b_addr[g] + bhoff + ko);
            #pragma unroll
            for (int g = 0; g < 4; g++) {      // term 1: ah*wh (16 indep)
                MMA_BF16(c[0][2*g+0], ah0[0],ah0[1],ah0[2],ah0[3], bb[g][0],bb[g][2]);
                MMA_BF16(c[0][2*g+1], ah0[0],ah0[1],ah0[2],ah0[3], bb[g][1],bb[g][3]);
                MMA_BF16(c[1][2*g+0], ah1[0],ah1[1],ah1[2],ah1[3], bb[g][0],bb[g][2]);
                MMA_BF16(c[1][2*g+1], ah1[0],ah1[1],ah1[2],ah1[3], bb[g][1],bb[g][3]);
            }
            #pragma unroll
            for (int g = 0; g < 4; g++) {      // term 2: al*wh (16 indep)
                MMA_BF16(c[0][2*g+0], al0[0],al0[1],al0[2],al0[3], bb[g][0],bb[g][2]);
                MMA_BF16(c[0][2*g+1], al0[0],al0[1],al0[2],al0[3], bb[g][1],bb[g][3]);
                MMA_BF16(c[1][2*g+0], al1[0],al1[1],al1[2],al1[3], bb[g][0],bb[g][2]);
                MMA_BF16(c[1][2*g+1], al1[0],al1[1],al1[2],al1[3], bb[g][1],bb[g][3]);
            }
            // lo weight plane
            #pragma unroll
            for (int g = 0; g < 4; g++)
                LDSM4(bb[g][0],bb[g][1],bb[g][2],bb[g][3], b_addr[g] + bhoff + BPL + ko);
            #pragma unroll
            for (int g = 0; g < 4; g++) {      // term 3: ah*wl (16 indep)
                MMA_BF16(c[0][2*g+0], ah0[0],ah0[1],ah0[2],ah0[3], bb[g][0],bb[g][2]);
                MMA_BF16(c[0][2*g+1], ah0[0],ah0[1],ah0[2],ah0[3], bb[g][1],bb[g][3]);
                MMA_BF16(c[1][2*g+0], ah1[0],ah1[1],ah1[2],ah1[3], bb[g][0],bb[g][2]);
                MMA_BF16(c[1][2*g+1], ah1[0],ah1[1],ah1[2],ah1[3], bb[g][1],bb[g][3]);
            }
        }
        __syncthreads();
    }

    // ---- epilogue ----
    const int gid = lane >> 2, tig = lane & 3;
    float s0[8], s1[8], q0[8], q1[8];
    if (MODE == 3) {
        #pragma unroll
        for (int nf = 0; nf < 8; nf++) { s0[nf]=0.f; s1[nf]=0.f; q0[nf]=0.f; q1[nf]=0.f; }
    }
    #pragma unroll
    for (int mf = 0; mf < 2; mf++) {
        #pragma unroll
        for (int half = 0; half < 2; half++) {
            int m = wm*32 + mf*16 + half*8 + gid;
            int gr = brow + m;
            float lp = 0.f; int isr = 0, nd = 0;
            if (MODE == 2) {
                int sub = gr >> 6;
                lp = logp[sub];
                isr = ((gr & 63) == rootl[sub]) ? 1 : 0;
            }
            if (MODE == 0) nd = aidx[gr];
            #pragma unroll
            for (int nf = 0; nf < 8; nf++) {
                int n0 = wn*64 + nf*8 + tig*2;
                float v0 = c[mf][nf][half*2+0] + bp[n0];
                float v1 = c[mf][nf][half*2+1] + bp[n0+1];
                if (MODE == 2) {
                    v0 += lp * g_vlogp[n0]   + g_root[isr*HH + n0];
                    v1 += lp * g_vlogp[n0+1] + g_root[isr*HH + n0+1];
                }
                if (MODE == 1 || MODE == 3) { v0 = fmaxf(v0, 0.f); v1 = fmaxf(v1, 0.f); }
                if (MODE == 2 || MODE == 3) {
                    float2 o; o.x = v0; o.y = v1;
                    *(float2*)(Cout + (size_t)gr*HH + n0) = o;
                }
                if (MODE == 0 || MODE == 1) {
                    u32 hi, lo; pack2(v0, v1, hi, lo);
                    *(u32*)(Cph + (size_t)gr*HH + n0) = hi;
                    *(u32*)(Cpl + (size_t)gr*HH + n0) = lo;
                }
                if (MODE == 0) {
                    atomicAdd(&g_xagg[(size_t)nd*HH + n0],     v0);
                    atomicAdd(&g_xagg[(size_t)nd*HH + n0 + 1], v1);
                }
                if (MODE == 3) {
                    s0[nf] += v0; s1[nf] += v1;
                    q0[nf] += v0*v0; q1[nf] += v1*v1;
                }
            }
        }
    }
    if (MODE == 3) {
        #pragma unroll
        for (int nf = 0; nf < 8; nf++) {
            #pragma unroll
            for (int off = 4; off < 32; off <<= 1) {
                s0[nf] += __shfl_xor_sync(0xFFFFFFFFu, s0[nf], off);
                s1[nf] += __shfl_xor_sync(0xFFFFFFFFu, s1[nf], off);
                q0[nf] += __shfl_xor_sync(0xFFFFFFFFu, q0[nf], off);
                q1[nf] += __shfl_xor_sync(0xFFFFFFFFu, q1[nf], off);
            }
        }
        if (gid == 0) {
            #pragma unroll
            for (int nf = 0; nf < 8; nf++) {
                int n0 = wn*64 + nf*8 + tig*2;
                atomicAdd(&g_stats[n0],      s0[nf]);
                atomicAdd(&g_stats[n0+1],    s1[nf]);
                atomicAdd(&g_stats[HH+n0],   q0[nf]);
                atomicAdd(&g_stats[HH+n0+1], q1[nf]);
            }
        }
    }
}

// ---------------- agg (optionally fused with previous layer's BN) ----------------
template<int FUSE_BN>
__global__ void __launch_bounds__(128)
agg_kernel(const float* __restrict__ u, float* __restrict__ H,
           u16* __restrict__ zph, u16* __restrict__ zpl,
           const int* __restrict__ esrc, const int* __restrict__ edst,
           const int* __restrict__ eptr, const float* __restrict__ geps,
           const float* __restrict__ gamma, const float* __restrict__ beta,
           int l)
{
    extern __shared__ float fsm[];
    float* hsm = fsm;              // [KK][HH]
    float* acc = fsm + KK*HH;      // [KK][HH]
    __shared__ int se[256], de[256];
    const int s = blockIdx.x;
    const int tid = threadIdx.x;
    const float eps1 = 1.f + geps[l];
    const size_t base = (size_t)s * KK;

    float g = 0.f, bt = 0.f, mu = 0.f;
    if (FUSE_BN) {
        const float invM = 1.f / (float)MROWS;
        mu = g_stats[tid] * invM;
        float var = g_stats[HH + tid] * invM - mu*mu;
        g = gamma[tid] * rsqrtf(var + 1e-5f);
        bt = beta[tid];
    }

    #pragma unroll 4
    for (int r = 0; r < KK; r++) {
        float hv;
        if (FUSE_BN) {
            float uv = u[(base + r)*HH + tid];
            hv = (uv - mu) * g + bt + H[(base + r)*HH + tid];
            H[(base + r)*HH + tid] = hv;
        } else {
            hv = H[(base + r)*HH + tid];
        }
        hsm[r*HH + tid] = hv;
        acc[r*HH + tid] = eps1 * hv;
    }
    __syncthreads();

    const int e0 = eptr[s], e1 = eptr[s+1];
    for (int eb = e0; eb < e1; eb += 256) {
        int ne = min(256, e1 - eb);
        for (int i = tid; i < ne; i += 128) {
            se[i] = esrc[eb + i];
            de[i] = edst[eb + i];
        }
        __syncthreads();
        for (int i = 0; i < ne; i++)
            acc[de[i]*HH + tid] += hsm[se[i]*HH + tid];
        __syncthreads();
    }

    #pragma unroll 4
    for (int r = 0; r < KK; r++) {
        u16 h, lo; splitf(acc[r*HH + tid], h, lo);
        zph[(base + r)*HH + tid] = h;
        zpl[(base + r)*HH + tid] = lo;
    }
}

// ---------------- final batchnorm apply ----------------
__global__ void bn_apply_kernel(const float* __restrict__ u, float* __restrict__ h,
                                const float* __restrict__ gamma, const float* __restrict__ beta) {
    int idx = blockIdx.x*blockDim.x + threadIdx.x;
    int c = idx & 127;
    const float invM = 1.f / (float)MROWS;
    float mu  = g_stats[c] * invM;
    float var = g_stats[HH + c] * invM - mu*mu;
    float g = gamma[c] * rsqrtf(var + 1e-5f);
    h[idx] = (u[idx] - mu) * g + beta[c] + h[idx];
}

// ---------------- launch ----------------
extern "C" void kernel_launch(void* const* d_in, const int* in_sizes, int n_in,
                              void* d_out, int out_size) {
    const float* x    = (const float*)d_in[0];
    const float* logp = (const float*)d_in[1];
    const float* npw  = (const float*)d_in[2];
    const float* npb  = (const float*)d_in[3];
    const float* lpw  = (const float*)d_in[4];
    const float* lpb  = (const float*)d_in[5];
    const float* remb = (const float*)d_in[6];
    const float* ipw  = (const float*)d_in[7];
    const float* ipb  = (const float*)d_in[8];
    const float* geps = (const float*)d_in[9];
    const float* w1   = (const float*)d_in[10];
    const float* b1   = (const float*)d_in[11];
    const float* w2   = (const float*)d_in[12];
    const float* b2   = (const float*)d_in[13];
    const float* mp2w = (const float*)d_in[14];
    const float* mp2b = (const float*)d_in[15];
    const float* bng  = (const float*)d_in[16];
    const float* bnb  = (const float*)d_in[17];
    const int* nodes  = (const int*)d_in[18];
    const int* rootl  = (const int*)d_in[19];
    const int* eidx   = (const int*)d_in[20];
    const int* eptr   = (const int*)d_in[21];
    float* hout = (float*)d_out;

    float *p_u;
    u16 *p_xph, *p_xpl, *p_zph, *p_zpl, *p_tph, *p_tpl, *p_z2h, *p_z2l;
    u16 *p_xah, *p_xal, *p_Mb, *p_w1b, *p_w2b, *p_mp2b;
    cudaGetSymbolAddress((void**)&p_u, g_u);
    cudaGetSymbolAddress((void**)&p_xph, g_xph);
    cudaGetSymbolAddress((void**)&p_xpl, g_xpl);
    cudaGetSymbolAddress((void**)&p_zph, g_zph);
    cudaGetSymbolAddress((void**)&p_zpl, g_zpl);
    cudaGetSymbolAddress((void**)&p_tph, g_tph);
    cudaGetSymbolAddress((void**)&p_tpl, g_tpl);
    cudaGetSymbolAddress((void**)&p_z2h, g_z2h);
    cudaGetSymbolAddress((void**)&p_z2l, g_z2l);
    cudaGetSymbolAddress((void**)&p_xah, g_xah);
    cudaGetSymbolAddress((void**)&p_xal, g_xal);
    cudaGetSymbolAddress((void**)&p_Mb, g_Mb);
    cudaGetSymbolAddress((void**)&p_w1b, g_w1b);
    cudaGetSymbolAddress((void**)&p_w2b, g_w2b);
    cudaGetSymbolAddress((void**)&p_mp2b, g_mp2b);

    const int SM1 = 2*BPL + 2*ABUF2;       // 110592
    const int SM3 = 4*BPL + 2*ABUF2;       // 180224
    const int SMA = 2*KK*HH*4;             // 65536
    cudaFuncSetAttribute(mma3_gemm<0>, cudaFuncAttributeMaxDynamicSharedMemorySize, SM1);
    cudaFuncSetAttribute(mma3_gemm<1>, cudaFuncAttributeMaxDynamicSharedMemorySize, SM1);
    cudaFuncSetAttribute(mma3_gemm<2>, cudaFuncAttributeMaxDynamicSharedMemorySize, SM1);
    cudaFuncSetAttribute(mma3_gemm<3>, cudaFuncAttributeMaxDynamicSharedMemorySize, SM3);
    cudaFuncSetAttribute(agg_kernel<0>, cudaFuncAttributeMaxDynamicSharedMemorySize, SMA);
    cudaFuncSetAttribute(agg_kernel<1>, cudaFuncAttributeMaxDynamicSharedMemorySize, SMA);

    const int* esrc = eidx;
    const int* edst = eidx + EE;

    // ---- prologue ----
    pack_x_kernel<<<(NN*HH)/256, 256>>>(x);
    fold_M_kernel<<<128, 128>>>(npw, ipw);
    fold_vec_kernel<<<1, 128>>>(lpw, npb, lpb, remb, ipw, ipb);
    pack_w128<<<dim3(64, LL), 256>>>(w1, p_w1b);
    pack_w128<<<dim3(64, LL), 256>>>(w2, p_w2b);
    pack_w256<<<dim3(128, LL), 256>>>(mp2w, p_mp2b);
    zero_cnt_kernel<<<(NN + 255)/256, 256>>>();
    count_kernel<<<MROWS/256, 256>>>(nodes);
    inv_kernel<<<(NN + 255)/256, 256>>>();
    zero_xagg_kernel<<<(NN*HH)/256, 256>>>();

    // ---- init ----
    mma3_gemm<2><<<MROWS/128, 256, SM1>>>(p_xph, p_xpl, p_Mb, hout,
                                          nullptr, nullptr, nullptr,
                                          nodes, nullptr, nullptr, logp, rootl);

    // ---- layers ----
    for (int l = 0; l < LL; l++) {
        if (l == 0)
            agg_kernel<0><<<SS, 128, SMA>>>(nullptr, hout, p_zph, p_zpl, esrc, edst,
                                            eptr, geps, nullptr, nullptr, l);
        else
            agg_kernel<1><<<SS, 128, SMA>>>(p_u, hout, p_zph, p_zpl, esrc, edst,
                                            eptr, geps, bng + (l-1)*HH, bnb + (l-1)*HH, l);

        mma3_gemm<1><<<MROWS/128, 256, SM1>>>(p_zph, p_zpl, p_w1b + (size_t)l*32768,
                                              nullptr, p_tph, p_tpl, b1 + l*HH,
                                              nullptr, nullptr, nullptr, nullptr, nullptr);
        mma3_gemm<0><<<MROWS/128, 256, SM1>>>(p_tph, p_tpl, p_w2b + (size_t)l*32768,
                                              nullptr, p_z2h, p_z2l, b2 + l*HH,
                                              nodes, nullptr, nullptr, nullptr, nullptr);

        pack_xagg_kernel<<<(NN*HH)/256, 256>>>();

        mma3_gemm<3><<<MROWS/128, 256, SM3>>>(p_z2h, p_z2l, p_mp2b + (size_t)l*65536,
                                              p_u, nullptr, nullptr, mp2b + l*HH,
                                              nodes, p_xah, p_xal, nullptr, nullptr);
    }

    // ---- final BN apply ----
    bn_apply_kernel<<<(MROWS*HH)/256, 256>>>(p_u, hout, bng + (LL-1)*HH, bnb + (LL-1)*HH);
}

// round 8
// speedup vs baseline: 1.4758x; 1.0181x over previous
#include <cuda_runtime.h>
#include <cuda_bf16.h>

#define NN     50000
#define SS     2048
#define KK     64
#define HH     128
#define EE     524288
#define LL     5
#define MROWS  (SS*KK)      // 131072
#define PL     34816        // smem plane: 128 rows x 272B

typedef unsigned short u16;
typedef unsigned int   u32;

// ---------------- scratch (device globals; no allocations) ----------------
__device__ u16 g_Mb[2*16384];          // folded init weight planes [hi][lo], [n][k]
__device__ u16 g_w1b[LL*2*16384];
__device__ u16 g_w2b[LL*2*16384];
__device__ u16 g_mp2b[LL*4*16384];     // [l][half][plane][n][k]
__device__ float g_vlogp[HH];
__device__ float g_bias0[HH];
__device__ float g_root[2*HH];
__device__ u16 g_xph[NN*HH],    g_xpl[NN*HH];
__device__ u16 g_zph[MROWS*HH], g_zpl[MROWS*HH];
__device__ u16 g_z2h[MROWS*HH], g_z2l[MROWS*HH];
__device__ u16 g_xah[NN*HH],    g_xal[NN*HH];
__device__ float g_u[MROWS*HH];
__device__ float g_xagg[NN*HH];
__device__ float g_inv[NN];
__device__ int   g_cnt[NN];
__device__ float g_stats[2*HH];

// ---------------- helpers ----------------
__device__ __forceinline__ void splitf(float v, u16& h, u16& l) {
    __nv_bfloat16 hb = __float2bfloat16_rn(v);
    __nv_bfloat16 lb = __float2bfloat16_rn(v - __bfloat162float(hb));
    h = __bfloat16_as_ushort(hb);
    l = __bfloat16_as_ushort(lb);
}
__device__ __forceinline__ void pack2(float v0, float v1, u32& hi, u32& lo) {
    u16 h0, l0, h1, l1;
    splitf(v0, h0, l0); splitf(v1, h1, l1);
    hi = (u32)h0 | ((u32)h1 << 16);
    lo = (u32)l0 | ((u32)l1 << 16);
}
__device__ __forceinline__ u32 smem_u32(const void* p) {
    u32 a;
    asm("{ .reg .u64 t; cvta.to.shared.u64 t, %1; cvt.u32.u64 %0, t; }" : "=r"(a) : "l"(p));
    return a;
}

#define CP16(dst, src) \
    asm volatile("cp.async.cg.shared.global [%0], [%1], 16;" :: "r"(dst), "l"(src) : "memory")
#define CPCOMMIT() asm volatile("cp.async.commit_group;" ::: "memory")
#define CPWAIT(n)  asm volatile("cp.async.wait_group %0;" :: "n"(n) : "memory")

#define LDSM4(R0,R1,R2,R3,ADDR) \
    asm volatile("ldmatrix.sync.aligned.m8n8.x4.shared.b16 {%0,%1,%2,%3}, [%4];" \
        : "=r"(R0),"=r"(R1),"=r"(R2),"=r"(R3) : "r"(ADDR))

#define MMA_BF16(C, A0,A1,A2,A3, B0,B1) \
    asm volatile("mma.sync.aligned.m16n8k16.row.col.f32.bf16.bf16.f32 " \
        "{%0,%1,%2,%3},{%4,%5,%6,%7},{%8,%9},{%0,%1,%2,%3};" \
        : "+f"(C[0]),"+f"(C[1]),"+f"(C[2]),"+f"(C[3]) \
        : "r"(A0),"r"(A1),"r"(A2),"r"(A3),"r"(B0),"r"(B1))

// ---- core: 128-k 3-term accumulate; A/B planes hi at base, lo at +PL ----
__device__ __forceinline__ void gemm128(u32 aB, u32 bB,
                                        const u32* ar, const u32* br,
                                        float c[2][8][4])
{
    #pragma unroll
    for (int ks = 0; ks < 8; ks++) {
        const u32 ko = ks*32;
        unsigned ah0[4], ah1[4], al0[4], al1[4], bb[4][4];
        LDSM4(ah0[0],ah0[1],ah0[2],ah0[3], aB + ar[0] + ko);
        LDSM4(ah1[0],ah1[1],ah1[2],ah1[3], aB + ar[1] + ko);
        LDSM4(al0[0],al0[1],al0[2],al0[3], aB + PL + ar[0] + ko);
        LDSM4(al1[0],al1[1],al1[2],al1[3], aB + PL + ar[1] + ko);
        #pragma unroll
        for (int g = 0; g < 4; g++)
            LDSM4(bb[g][0],bb[g][1],bb[g][2],bb[g][3], bB + br[g] + ko);
        #pragma unroll
        for (int g = 0; g < 4; g++) {
            MMA_BF16(c[0][2*g+0], ah0[0],ah0[1],ah0[2],ah0[3], bb[g][0],bb[g][2]);
            MMA_BF16(c[0][2*g+1], ah0[0],ah0[1],ah0[2],ah0[3], bb[g][1],bb[g][3]);
            MMA_BF16(c[1][2*g+0], ah1[0],ah1[1],ah1[2],ah1[3], bb[g][0],bb[g][2]);
            MMA_BF16(c[1][2*g+1], ah1[0],ah1[1],ah1[2],ah1[3], bb[g][1],bb[g][3]);
        }
        #pragma unroll
        for (int g = 0; g < 4; g++) {
            MMA_BF16(c[0][2*g+0], al0[0],al0[1],al0[2],al0[3], bb[g][0],bb[g][2]);
            MMA_BF16(c[0][2*g+1], al0[0],al0[1],al0[2],al0[3], bb[g][1],bb[g][3]);
            MMA_BF16(c[1][2*g+0], al1[0],al1[1],al1[2],al1[3], bb[g][0],bb[g][2]);
            MMA_BF16(c[1][2*g+1], al1[0],al1[1],al1[2],al1[3], bb[g][1],bb[g][3]);
        }
        #pragma unroll
        for (int g = 0; g < 4; g++)
            LDSM4(bb[g][0],bb[g][1],bb[g][2],bb[g][3], bB + PL + br[g] + ko);
        #pragma unroll
        for (int g = 0; g < 4; g++) {
            MMA_BF16(c[0][2*g+0], ah0[0],ah0[1],ah0[2],ah0[3], bb[g][0],bb[g][2]);
            MMA_BF16(c[0][2*g+1], ah0[0],ah0[1],ah0[2],ah0[3], bb[g][1],bb[g][3]);
            MMA_BF16(c[1][2*g+0], ah1[0],ah1[1],ah1[2],ah1[3], bb[g][0],bb[g][2]);
            MMA_BF16(c[1][2*g+1], ah1[0],ah1[1],ah1[2],ah1[3], bb[g][1],bb[g][3]);
        }
    }
}

__device__ __forceinline__ void frag_addrs(int lane, int wm, int wn, u32* ar, u32* br) {
    #pragma unroll
    for (int mf = 0; mf < 2; mf++) {
        int row = wm*32 + mf*16 + (lane & 15);
        ar[mf] = row*272 + (lane>>4)*16;
    }
    #pragma unroll
    for (int g = 0; g < 4; g++) {
        int row = wn*64 + g*16 + ((lane>>3)&1)*8 + (lane&7);
        br[g] = row*272 + (lane>>4)*16;
    }
}
#define ZERO_C(c) { _Pragma("unroll") for (int i=0;i<2;i++) _Pragma("unroll") \
    for (int j=0;j<8;j++) _Pragma("unroll") for (int q=0;q<4;q++) (c)[i][j][q]=0.f; }

// ---------------- packing kernels ----------------
__global__ void pack_x_kernel(const float* __restrict__ x) {
    int idx = blockIdx.x*256 + threadIdx.x;
    u16 h, l; splitf(x[idx], h, l);
    g_xph[idx] = h; g_xpl[idx] = l;
}
__global__ void fold_M_kernel(const float* __restrict__ npw, const float* __restrict__ ipw) {
    int k = blockIdx.x, n = threadIdx.x;
    float s = 0.f;
    for (int c = 0; c < HH; c++) s += npw[k*HH + c] * ipw[c*HH + n];
    u16 h, l; splitf(s, h, l);
    g_Mb[n*128 + k] = h; g_Mb[16384 + n*128 + k] = l;
}
__global__ void fold_vec_kernel(const float* __restrict__ lpw, const float* __restrict__ npb,
                                const float* __restrict__ lpb, const float* __restrict__ remb,
                                const float* __restrict__ ipw, const float* __restrict__ ipb) {
    int j = threadIdx.x;
    float v = 0.f, b = ipb[j], r0 = 0.f, r1 = 0.f;
    for (int k = 0; k < HH; k++) {
        float wa = ipw[k*HH + j];
        float wb = ipw[(HH + k)*HH + j];
        float wc = ipw[(2*HH + k)*HH + j];
        v  += lpw[k] * wb;
        b  += npb[k] * wa + lpb[k] * wb;
        r0 += remb[k] * wc;
        r1 += remb[HH + k] * wc;
    }
    g_vlogp[j] = v; g_bias0[j] = b; g_root[j] = r0; g_root[HH + j] = r1;
}
__global__ void pack_w128(const float* __restrict__ W, u16* __restrict__ out) {
    int l = blockIdx.y;
    int idx = blockIdx.x*256 + threadIdx.x;
    int k = idx >> 7, n = idx & 127;
    u16 h, lo; splitf(W[(size_t)l*16384 + idx], h, lo);
    out[(size_t)l*32768 + n*128 + k] = h;
    out[(size_t)l*32768 + 16384 + n*128 + k] = lo;
}
__global__ void pack_w256(const float* __restrict__ W, u16* __restrict__ out) {
    int l = blockIdx.y;
    int idx = blockIdx.x*256 + threadIdx.x;
    int kg = idx >> 7, n = idx & 127;
    int half = kg >> 7, kl = kg & 127;
    u16 h, lo; splitf(W[(size_t)l*32768 + idx], h, lo);
    out[(size_t)l*65536 + half*32768 + n*128 + kl] = h;
    out[(size_t)l*65536 + half*32768 + 16384 + n*128 + kl] = lo;
}

// ---------------- counts ----------------
__global__ void zero_cnt_kernel() {
    int i = blockIdx.x*blockDim.x + threadIdx.x;
    if (i < NN) g_cnt[i] = 0;
}
__global__ void count_kernel(const int* __restrict__ nodes) {
    int i = blockIdx.x*blockDim.x + threadIdx.x;
    if (i < MROWS) atomicAdd(&g_cnt[nodes[i]], 1);
}
__global__ void inv_kernel() {
    int i = blockIdx.x*blockDim.x + threadIdx.x;
    if (i < NN) g_inv[i] = 1.f / (float)max(g_cnt[i], 1);
}
__global__ void zero_xagg_kernel() {
    int i = blockIdx.x*blockDim.x + threadIdx.x;
    g_xagg[i] = 0.f;
    if (i < 2*HH) g_stats[i] = 0.f;
}
__global__ void pack_xagg_kernel() {
    int idx = blockIdx.x*256 + threadIdx.x;
    int row = idx >> 7;
    float v = g_xagg[idx] * g_inv[row];
    u16 h, l; splitf(v, h, l);
    g_xah[idx] = h; g_xal[idx] = l;
    g_xagg[idx] = 0.f;
    if (blockIdx.x == 0 && threadIdx.x < 2*HH) g_stats[threadIdx.x] = 0.f;
}

// ---------------- init GEMM: h = gather(x)@M + lp*v + root + bias0 ----------------
__global__ void __launch_bounds__(256, 1)
init_gemm(const float* __restrict__ logp, const int* __restrict__ rootl,
          const int* __restrict__ nodes, float* __restrict__ Cout)
{
    extern __shared__ __align__(16) char sm[];
    const u32 sb = smem_u32(sm);          // B (M) 2 planes
    const u32 atB = sb + 2*PL;            // A 2 planes
    const int tid = threadIdx.x, lane = tid & 31, warp = tid >> 5;
    const int wm = warp & 3, wn = warp >> 2;
    const int brow = blockIdx.x * 128;

    #pragma unroll
    for (int it = 0; it < 16; it++) {     // B: g_Mb
        int ch = tid + it*256;
        int pl = ch >> 11, rem = ch & 2047, r = rem >> 4, q = rem & 15;
        CP16(sb + pl*PL + r*272 + q*16, g_Mb + (size_t)pl*16384 + r*128 + q*8);
    }
    #pragma unroll
    for (int it = 0; it < 16; it++) {     // A: gathered x planes
        int ch = tid + it*256;
        int pl = ch >> 11, rem = ch & 2047, r = rem >> 4, q = rem & 15;
        const u16* src = (pl ? g_xpl : g_xph) + (size_t)nodes[brow + r]*HH + q*8;
        CP16(atB + pl*PL + r*272 + q*16, src);
    }
    CPCOMMIT();

    u32 ar[2], br[4];
    frag_addrs(lane, wm, wn, ar, br);
    float c[2][8][4]; ZERO_C(c);

    CPWAIT(0); __syncthreads();
    gemm128(atB, sb, ar, br, c);

    const int gid = lane >> 2, tig = lane & 3;
    #pragma unroll
    for (int mf = 0; mf < 2; mf++) {
        #pragma unroll
        for (int half = 0; half < 2; half++) {
            int gr = brow + wm*32 + mf*16 + half*8 + gid;
            int sub = gr >> 6;
            float lp = logp[sub];
            int isr = ((gr & 63) == rootl[sub]) ? 1 : 0;
            #pragma unroll
            for (int nf = 0; nf < 8; nf++) {
                int n0 = wn*64 + nf*8 + tig*2;
                float v0 = c[mf][nf][half*2+0] + g_bias0[n0]
                         + lp * g_vlogp[n0]   + g_root[isr*HH + n0];
                float v1 = c[mf][nf][half*2+1] + g_bias0[n0+1]
                         + lp * g_vlogp[n0+1] + g_root[isr*HH + n0+1];
                float2 o; o.x = v0; o.y = v1;
                *(float2*)(Cout + (size_t)gr*HH + n0) = o;
            }
        }
    }
}

// ---------------- fused layer kernel: t = relu(z@W1+b1); z2 = t@W2+b2 ----------------
// epilogue2: pack z2 planes + scatter atomics to g_xagg
__global__ void __launch_bounds__(256, 1)
layer12_kernel(const u16* __restrict__ w1b, const u16* __restrict__ w2b,
               const float* __restrict__ b1, const float* __restrict__ b2,
               const int* __restrict__ aidx)
{
    extern __shared__ __align__(16) char sm[];
    const u32 sb = smem_u32(sm);          // W1 planes [0,PL); W2 planes [2PL,4PL)
    const u32 atB = sb + 4*PL;            // z / t planes
    const int tid = threadIdx.x, lane = tid & 31, warp = tid >> 5;
    const int wm = warp & 3, wn = warp >> 2;
    const int brow = blockIdx.x * 128;

    #pragma unroll
    for (int it = 0; it < 16; it++) {     // A = z planes
        int ch = tid + it*256;
        int pl = ch >> 11, rem = ch & 2047, r = rem >> 4, q = rem & 15;
        const u16* src = (pl ? g_zpl : g_zph) + (size_t)(brow + r)*HH + q*8;
        CP16(atB + pl*PL + r*272 + q*16, src);
    }
    #pragma unroll
    for (int it = 0; it < 16; it++) {     // W1
        int ch = tid + it*256;
        int pl = ch >> 11, rem = ch & 2047, r = rem >> 4, q = rem & 15;
        CP16(sb + pl*PL + r*272 + q*16, w1b + (size_t)pl*16384 + r*128 + q*8);
    }
    CPCOMMIT();
    #pragma unroll
    for (int it = 0; it < 16; it++) {     // W2 (overlaps GEMM1)
        int ch = tid + it*256;
        int pl = ch >> 11, rem = ch & 2047, r = rem >> 4, q = rem & 15;
        CP16(sb + 2*PL + pl*PL + r*272 + q*16, w2b + (size_t)pl*16384 + r*128 + q*8);
    }
    CPCOMMIT();

    u32 ar[2], br[4];
    frag_addrs(lane, wm, wn, ar, br);
    float c[2][8][4]; ZERO_C(c);

    CPWAIT(1); __syncthreads();
    gemm128(atB, sb, ar, br, c);          // GEMM1: z @ W1

    CPWAIT(0); __syncthreads();           // all z reads done; W2 visible

    // epilogue1: t = relu(c + b1) -> split -> smem t planes (overwrite z)
    const int gid = lane >> 2, tig = lane & 3;
    #pragma unroll
    for (int mf = 0; mf < 2; mf++) {
        #pragma unroll
        for (int half = 0; half < 2; half++) {
            int m = wm*32 + mf*16 + half*8 + gid;
            #pragma unroll
            for (int nf = 0; nf < 8; nf++) {
                int n0 = wn*64 + nf*8 + tig*2;
                float v0 = fmaxf(c[mf][nf][half*2+0] + b1[n0],   0.f);
                float v1 = fmaxf(c[mf][nf][half*2+1] + b1[n0+1], 0.f);
                u32 hi, lo; pack2(v0, v1, hi, lo);
                u32 off = m*272 + n0*2;
                *(u32*)(sm + (atB - sb) + off)      = hi;
                *(u32*)(sm + (atB - sb) + PL + off) = lo;
            }
        }
    }
    __syncthreads();

    ZERO_C(c);
    gemm128(atB, sb + 2*PL, ar, br, c);   // GEMM2: t @ W2

    // epilogue2: z2 planes + scatter
    #pragma unroll
    for (int mf = 0; mf < 2; mf++) {
        #pragma unroll
        for (int half = 0; half < 2; half++) {
            int gr = brow + wm*32 + mf*16 + half*8 + gid;
            int nd = aidx[gr];
            #pragma unroll
            for (int nf = 0; nf < 8; nf++) {
                int n0 = wn*64 + nf*8 + tig*2;
                float v0 = c[mf][nf][half*2+0] + b2[n0];
                float v1 = c[mf][nf][half*2+1] + b2[n0+1];
                u32 hi, lo; pack2(v0, v1, hi, lo);
                *(u32*)(g_z2h + (size_t)gr*HH + n0) = hi;
                *(u32*)(g_z2l + (size_t)gr*HH + n0) = lo;
                atomicAdd(&g_xagg[(size_t)nd*HH + n0],     v0);
                atomicAdd(&g_xagg[(size_t)nd*HH + n0 + 1], v1);
            }
        }
    }
}

// ---------------- mp2 kernel: u = relu([z2 | xagg-gather]@Wmp2 + b) + bn stats ----------------
__global__ void __launch_bounds__(256, 1)
mp2_kernel(const u16* __restrict__ blob, const float* __restrict__ bias,
           const int* __restrict__ aidx, float* __restrict__ uout)
{
    extern __shared__ __align__(16) char sm[];
    const u32 sb = smem_u32(sm);          // B half0 planes [0,2PL), half1 [2PL,4PL)
    const u32 atB = sb + 4*PL;            // A planes (reused for both halves)
    const int tid = threadIdx.x, lane = tid & 31, warp = tid >> 5;
    const int wm = warp & 3, wn = warp >> 2;
    const int brow = blockIdx.x * 128;

    #pragma unroll
    for (int it = 0; it < 16; it++) {     // A = z2 planes (dense half)
        int ch = tid + it*256;
        int pl = ch >> 11, rem = ch & 2047, r = rem >> 4, q = rem & 15;
        const u16* src = (pl ? g_z2l : g_z2h) + (size_t)(brow + r)*HH + q*8;
        CP16(atB + pl*PL + r*272 + q*16, src);
    }
    #pragma unroll
    for (int it = 0; it < 16; it++) {     // B half0
        int ch = tid + it*256;
        int pl = ch >> 11, rem = ch & 2047, r = rem >> 4, q = rem & 15;
        CP16(sb + pl*PL + r*272 + q*16, blob + (size_t)pl*16384 + r*128 + q*8);
    }
    CPCOMMIT();
    #pragma unroll
    for (int it = 0; it < 16; it++) {     // B half1
        int ch = tid + it*256;
        int pl = ch >> 11, rem = ch & 2047, r = rem >> 4, q = rem & 15;
        CP16(sb + 2*PL + pl*PL + r*272 + q*16,
             blob + 32768 + (size_t)pl*16384 + r*128 + q*8);
    }
    CPCOMMIT();

    u32 ar[2], br[4];
    frag_addrs(lane, wm, wn, ar, br);
    float c[2][8][4]; ZERO_C(c);

    CPWAIT(1); __syncthreads();
    gemm128(atB, sb, ar, br, c);          // phase 1: z2 @ W[half0]

    __syncthreads();                      // all reads of A region done
    #pragma unroll
    for (int it = 0; it < 16; it++) {     // A = gathered xagg planes
        int ch = tid + it*256;
        int pl = ch >> 11, rem = ch & 2047, r = rem >> 4, q = rem & 15;
        const u16* src = (pl ? g_xal : g_xah) + (size_t)aidx[brow + r]*HH + q*8;
        CP16(atB + pl*PL + r*272 + q*16, src);
    }
    CPCOMMIT();
    CPWAIT(0); __syncthreads();
    gemm128(atB, sb + 2*PL, ar, br, c);   // phase 2: accumulate gathered @ W[half1]

    // epilogue: relu + bias -> uout, fused bn stats
    const int gid = lane >> 2, tig = lane & 3;
    float s0[8], s1[8], q0[8], q1[8];
    #pragma unroll
    for (int nf = 0; nf < 8; nf++) { s0[nf]=0.f; s1[nf]=0.f; q0[nf]=0.f; q1[nf]=0.f; }
    #pragma unroll
    for (int mf = 0; mf < 2; mf++) {
        #pragma unroll
        for (int half = 0; half < 2; half++) {
            int gr = brow + wm*32 + mf*16 + half*8 + gid;
            #pragma unroll
            for (int nf = 0; nf < 8; nf++) {
                int n0 = wn*64 + nf*8 + tig*2;
                float v0 = fmaxf(c[mf][nf][half*2+0] + bias[n0],   0.f);
                float v1 = fmaxf(c[mf][nf][half*2+1] + bias[n0+1], 0.f);
                float2 o; o.x = v0; o.y = v1;
                *(float2*)(uout + (size_t)gr*HH + n0) = o;
                s0[nf] += v0; s1[nf] += v1;
                q0[nf] += v0*v0; q1[nf] += v1*v1;
            }
        }
    }
    #pragma unroll
    for (int nf = 0; nf < 8; nf++) {
        #pragma unroll
        for (int off = 4; off < 32; off <<= 1) {
            s0[nf] += __shfl_xor_sync(0xFFFFFFFFu, s0[nf], off);
            s1[nf] += __shfl_xor_sync(0xFFFFFFFFu, s1[nf], off);
            q0[nf] += __shfl_xor_sync(0xFFFFFFFFu, q0[nf], off);
            q1[nf] += __shfl_xor_sync(0xFFFFFFFFu, q1[nf], off);
        }
    }
    if (gid == 0) {
        #pragma unroll
        for (int nf = 0; nf < 8; nf++) {
            int n0 = wn*64 + nf*8 + tig*2;
            atomicAdd(&g_stats[n0],      s0[nf]);
            atomicAdd(&g_stats[n0+1],    s1[nf]);
            atomicAdd(&g_stats[HH+n0],   q0[nf]);
            atomicAdd(&g_stats[HH+n0+1], q1[nf]);
        }
    }
}

// ---------------- agg (optionally fused with previous layer's BN) ----------------
template<int FUSE_BN>
__global__ void __launch_bounds__(128)
agg_kernel(const float* __restrict__ u, float* __restrict__ H,
           u16* __restrict__ zph, u16* __restrict__ zpl,
           const int* __restrict__ esrc, const int* __restrict__ edst,
           const int* __restrict__ eptr, const float* __restrict__ geps,
           const float* __restrict__ gamma, const float* __restrict__ beta,
           int l)
{
    extern __shared__ float fsm[];
    float* hsm = fsm;              // [KK][HH]
    float* acc = fsm + KK*HH;      // [KK][HH]
    __shared__ int se[256], de[256];
    const int s = blockIdx.x;
    const int tid = threadIdx.x;
    const float eps1 = 1.f + geps[l];
    const size_t base = (size_t)s * KK;

    float g = 0.f, bt = 0.f, mu = 0.f;
    if (FUSE_BN) {
        const float invM = 1.f / (float)MROWS;
        mu = g_stats[tid] * invM;
        float var = g_stats[HH + tid] * invM - mu*mu;
        g = gamma[tid] * rsqrtf(var + 1e-5f);
        bt = beta[tid];
    }

    #pragma unroll 4
    for (int r = 0; r < KK; r++) {
        float hv;
        if (FUSE_BN) {
            float uv = u[(base + r)*HH + tid];
            hv = (uv - mu) * g + bt + H[(base + r)*HH + tid];
            H[(base + r)*HH + tid] = hv;
        } else {
            hv = H[(base + r)*HH + tid];
        }
        hsm[r*HH + tid] = hv;
        acc[r*HH + tid] = eps1 * hv;
    }
    __syncthreads();

    const int e0 = eptr[s], e1 = eptr[s+1];
    for (int eb = e0; eb < e1; eb += 256) {
        int ne = min(256, e1 - eb);
        for (int i = tid; i < ne; i += 128) {
            se[i] = esrc[eb + i];
            de[i] = edst[eb + i];
        }
        __syncthreads();
        for (int i = 0; i < ne; i++)
            acc[de[i]*HH + tid] += hsm[se[i]*HH + tid];
        __syncthreads();
    }

    #pragma unroll 4
    for (int r = 0; r < KK; r++) {
        u16 h, lo; splitf(acc[r*HH + tid], h, lo);
        zph[(base + r)*HH + tid] = h;
        zpl[(base + r)*HH + tid] = lo;
    }
}

// ---------------- final batchnorm apply ----------------
__global__ void bn_apply_kernel(const float* __restrict__ u, float* __restrict__ h,
                                const float* __restrict__ gamma, const float* __restrict__ beta) {
    int idx = blockIdx.x*blockDim.x + threadIdx.x;
    int c = idx & 127;
    const float invM = 1.f / (float)MROWS;
    float mu  = g_stats[c] * invM;
    float var = g_stats[HH + c] * invM - mu*mu;
    float g = gamma[c] * rsqrtf(var + 1e-5f);
    h[idx] = (u[idx] - mu) * g + beta[c] + h[idx];
}

// ---------------- launch ----------------
extern "C" void kernel_launch(void* const* d_in, const int* in_sizes, int n_in,
                              void* d_out, int out_size) {
    const float* x    = (const float*)d_in[0];
    const float* logp = (const float*)d_in[1];
    const float* npw  = (const float*)d_in[2];
    const float* npb  = (const float*)d_in[3];
    const float* lpw  = (const float*)d_in[4];
    const float* lpb  = (const float*)d_in[5];
    const float* remb = (const float*)d_in[6];
    const float* ipw  = (const float*)d_in[7];
    const float* ipb  = (const float*)d_in[8];
    const float* geps = (const float*)d_in[9];
    const float* w1   = (const float*)d_in[10];
    const float* b1   = (const float*)d_in[11];
    const float* w2   = (const float*)d_in[12];
    const float* b2   = (const float*)d_in[13];
    const float* mp2w = (const float*)d_in[14];
    const float* mp2b = (const float*)d_in[15];
    const float* bng  = (const float*)d_in[16];
    const float* bnb  = (const float*)d_in[17];
    const int* nodes  = (const int*)d_in[18];
    const int* rootl  = (const int*)d_in[19];
    const int* eidx   = (const int*)d_in[20];
    const int* eptr   = (const int*)d_in[21];
    float* hout = (float*)d_out;

    float *p_u;
    u16 *p_zph, *p_zpl, *p_w1b, *p_w2b, *p_mp2b;
    cudaGetSymbolAddress((void**)&p_u, g_u);
    cudaGetSymbolAddress((void**)&p_zph, g_zph);
    cudaGetSymbolAddress((void**)&p_zpl, g_zpl);
    cudaGetSymbolAddress((void**)&p_w1b, g_w1b);
    cudaGetSymbolAddress((void**)&p_w2b, g_w2b);
    cudaGetSymbolAddress((void**)&p_mp2b, g_mp2b);

    const int SM_INIT  = 4*PL;            // 139264
    const int SM_LAYER = 6*PL;            // 208896
    const int SMA = 2*KK*HH*4;            // 65536
    cudaFuncSetAttribute(init_gemm,      cudaFuncAttributeMaxDynamicSharedMemorySize, SM_INIT);
    cudaFuncSetAttribute(layer12_kernel, cudaFuncAttributeMaxDynamicSharedMemorySize, SM_LAYER);
    cudaFuncSetAttribute(mp2_kernel,     cudaFuncAttributeMaxDynamicSharedMemorySize, SM_LAYER);
    cudaFuncSetAttribute(agg_kernel<0>,  cudaFuncAttributeMaxDynamicSharedMemorySize, SMA);
    cudaFuncSetAttribute(agg_kernel<1>,  cudaFuncAttributeMaxDynamicSharedMemorySize, SMA);

    const int* esrc = eidx;
    const int* edst = eidx + EE;

    // ---- prologue ----
    pack_x_kernel<<<(NN*HH)/256, 256>>>(x);
    fold_M_kernel<<<128, 128>>>(npw, ipw);
    fold_vec_kernel<<<1, 128>>>(lpw, npb, lpb, remb, ipw, ipb);
    pack_w128<<<dim3(64, LL), 256>>>(w1, p_w1b);
    pack_w128<<<dim3(64, LL), 256>>>(w2, p_w2b);
    pack_w256<<<dim3(128, LL), 256>>>(mp2w, p_mp2b);
    zero_cnt_kernel<<<(NN + 255)/256, 256>>>();
    count_kernel<<<MROWS/256, 256>>>(nodes);
    inv_kernel<<<(NN + 255)/256, 256>>>();
    zero_xagg_kernel<<<(NN*HH)/256, 256>>>();

    // ---- init ----
    init_gemm<<<MROWS/128, 256, SM_INIT>>>(logp, rootl, nodes, hout);

    // ---- layers ----
    for (int l = 0; l < LL; l++) {
        if (l == 0)
            agg_kernel<0><<<SS, 128, SMA>>>(nullptr, hout, p_zph, p_zpl, esrc, edst,
                                            eptr, geps, nullptr, nullptr, l);
        else
            agg_kernel<1><<<SS, 128, SMA>>>(p_u, hout, p_zph, p_zpl, esrc, edst,
                                            eptr, geps, bng + (l-1)*HH, bnb + (l-1)*HH, l);

        layer12_kernel<<<MROWS/128, 256, SM_LAYER>>>(p_w1b + (size_t)l*32768,
                                                     p_w2b + (size_t)l*32768,
                                                     b1 + l*HH, b2 + l*HH, nodes);

        pack_xagg_kernel<<<(NN*HH)/256, 256>>>();

        mp2_kernel<<<MROWS/128, 256, SM_LAYER>>>(p_mp2b + (size_t)l*65536,
                                                 mp2b + l*HH, nodes, p_u);
    }

    // ---- final BN apply ----
    bn_apply_kernel<<<(MROWS*HH)/256, 256>>>(p_u, hout, bng + (LL-1)*HH, bnb + (LL-1)*HH);
}